// round 1
// baseline (speedup 1.0000x reference)
#include <cuda_runtime.h>
#include <math.h>

#define Bc   16
#define Hh   56
#define Wd   56
#define Cch  256
#define C4c  64
#define Gg   8
#define GKK  72
#define HWp  (Hh*Wd)      // 3136
#define Nn   (Bc*HWp)     // 50176
#define EPSv 1e-5f

// ---- scratch (device globals: allocation-free rule) ----
__device__ float g_t[(size_t)Nn*C4c];       // 12.8 MB
__device__ float g_wk[(size_t)Nn*GKK];      // 14.5 MB
__device__ float g_hw[(size_t)Nn*Cch];      // 51.4 MB
__device__ float g_cc[(size_t)Nn*Cch];      // 51.4 MB
__device__ float g_sum[C4c];
__device__ float g_sumsq[C4c];
__device__ float g_asum[Bc*Cch];
__device__ float g_a0[Bc*Cch];
__device__ float g_a1[Bc*Cch];

__global__ void k_zero() {
    int tid = threadIdx.x;
    if (tid < C4c) { g_sum[tid] = 0.f; g_sumsq[tid] = 0.f; }
    for (int i = tid; i < Bc*Cch; i += 256) g_asum[i] = 0.f;
}

// ---------- GEMM1: t[N,64] = x[N,256] @ conv1_w[64,256]^T + b ; fused BN stats ----------
__global__ __launch_bounds__(256) void k_gemm1(const float* __restrict__ x,
                                               const float* __restrict__ w1,
                                               const float* __restrict__ b1) {
    __shared__ float As[16][64];
    __shared__ float Bs[16][64];
    __shared__ float scol[64];
    __shared__ float ssq[64];
    int tid = threadIdx.x, tx = tid & 15, ty = tid >> 4;
    int row0 = blockIdx.x * 64;
    float acc[4][4] = {};
    int r = tid >> 2, kq = (tid & 3) * 4;
    for (int k0 = 0; k0 < 256; k0 += 16) {
        float4 v = *(const float4*)&x[(size_t)(row0 + r) * 256 + k0 + kq];
        As[kq+0][r] = v.x; As[kq+1][r] = v.y; As[kq+2][r] = v.z; As[kq+3][r] = v.w;
        float4 u = *(const float4*)&w1[(size_t)r * 256 + k0 + kq];
        Bs[kq+0][r] = u.x; Bs[kq+1][r] = u.y; Bs[kq+2][r] = u.z; Bs[kq+3][r] = u.w;
        __syncthreads();
        #pragma unroll
        for (int k = 0; k < 16; k++) {
            float4 a = *(float4*)&As[k][ty*4];
            float4 b = *(float4*)&Bs[k][tx*4];
            acc[0][0] += a.x*b.x; acc[0][1] += a.x*b.y; acc[0][2] += a.x*b.z; acc[0][3] += a.x*b.w;
            acc[1][0] += a.y*b.x; acc[1][1] += a.y*b.y; acc[1][2] += a.y*b.z; acc[1][3] += a.y*b.w;
            acc[2][0] += a.z*b.x; acc[2][1] += a.z*b.y; acc[2][2] += a.z*b.z; acc[2][3] += a.z*b.w;
            acc[3][0] += a.w*b.x; acc[3][1] += a.w*b.y; acc[3][2] += a.w*b.z; acc[3][3] += a.w*b.w;
        }
        __syncthreads();
    }
    float bb0 = b1[tx*4+0], bb1 = b1[tx*4+1], bb2 = b1[tx*4+2], bb3 = b1[tx*4+3];
    float cs[4] = {0,0,0,0}, cq[4] = {0,0,0,0};
    #pragma unroll
    for (int i = 0; i < 4; i++) {
        int rr = row0 + ty*4 + i;
        float4 vv;
        vv.x = acc[i][0] + bb0; vv.y = acc[i][1] + bb1;
        vv.z = acc[i][2] + bb2; vv.w = acc[i][3] + bb3;
        *(float4*)&g_t[(size_t)rr * 64 + tx*4] = vv;
        cs[0] += vv.x; cs[1] += vv.y; cs[2] += vv.z; cs[3] += vv.w;
        cq[0] += vv.x*vv.x; cq[1] += vv.y*vv.y; cq[2] += vv.z*vv.z; cq[3] += vv.w*vv.w;
    }
    if (tid < 64) { scol[tid] = 0.f; ssq[tid] = 0.f; }
    __syncthreads();
    #pragma unroll
    for (int j = 0; j < 4; j++) {
        atomicAdd(&scol[tx*4+j], cs[j]);
        atomicAdd(&ssq[tx*4+j],  cq[j]);
    }
    __syncthreads();
    if (tid < 64) {
        atomicAdd(&g_sum[tid],   scol[tid]);
        atomicAdd(&g_sumsq[tid], ssq[tid]);
    }
}

// ---------- BN + relu + kernel-gen GEMM: w[N,72] = relu(bn(t)) @ conv2_w[72,64]^T + b ----------
__global__ __launch_bounds__(256) void k_kgen(const float* __restrict__ gamma,
                                              const float* __restrict__ beta,
                                              const float* __restrict__ w2,
                                              const float* __restrict__ b2) {
    __shared__ float ts[64][65];
    __shared__ float ws[72][65];
    int tid = threadIdx.x;
    int row0 = blockIdx.x * 64;
    for (int idx = tid; idx < 72*64; idx += 256) {
        int o = idx / 64, k = idx % 64;
        ws[o][k] = w2[idx];
    }
    const float invN = 1.0f / (float)Nn;
    for (int idx = tid; idx < 64*64; idx += 256) {
        int r = idx >> 6, ch = idx & 63;
        float mu  = g_sum[ch] * invN;
        float var = g_sumsq[ch] * invN - mu * mu;
        float v = g_t[(size_t)(row0 + r) * 64 + ch];
        v = gamma[ch] * (v - mu) * rsqrtf(var + EPSv) + beta[ch];
        ts[r][ch] = fmaxf(v, 0.f);
    }
    __syncthreads();
    #pragma unroll 2
    for (int j = 0; j < 18; j++) {
        int idx = tid + j * 256;
        int r = idx / 72, o = idx % 72;
        float acc = 0.f;
        #pragma unroll
        for (int k = 0; k < 64; k++) acc += ts[r][k] * ws[o][k];
        g_wk[(size_t)(row0 + r) * 72 + o] = acc + b2[o];
    }
}

// ---------- involution: hw[n,c] = sum_k w[n, g(c), k] * x[neighbor_k, c] ----------
__global__ __launch_bounds__(256) void k_invo(const float* __restrict__ x) {
    __shared__ float wsh[72];
    int n = blockIdx.x;
    int tid = threadIdx.x;
    if (tid < 72) wsh[tid] = g_wk[(size_t)n * 72 + tid];
    __syncthreads();
    int b = n / HWp, hw = n % HWp, h = hw / Wd, w = hw % Wd;
    int g9 = (tid >> 5) * 9;
    float acc = 0.f;
    #pragma unroll
    for (int dy = -1; dy <= 1; dy++) {
        int hh = h + dy;
        if (hh < 0 || hh >= Hh) continue;
        #pragma unroll
        for (int dx = -1; dx <= 1; dx++) {
            int ww = w + dx;
            if (ww < 0 || ww >= Wd) continue;
            acc += wsh[g9 + (dy+1)*3 + (dx+1)] *
                   x[((size_t)(b*Hh + hh)*Wd + ww)*256 + tid];
        }
    }
    g_hw[(size_t)n * 256 + tid] = acc;
}

// ---------- GEMM c = x @ mlp_c_w^T ; fused (hw+c) spatial-mean accumulation ----------
__global__ __launch_bounds__(256) void k_gemm_c(const float* __restrict__ x,
                                                const float* __restrict__ wm) {
    __shared__ float As[16][64];
    __shared__ float Bs[16][64];
    __shared__ float scol[64];
    int tid = threadIdx.x, tx = tid & 15, ty = tid >> 4;
    int row0 = blockIdx.x * 64, o0 = blockIdx.y * 64;
    float acc[4][4] = {};
    int r = tid >> 2, kq = (tid & 3) * 4;
    for (int k0 = 0; k0 < 256; k0 += 16) {
        float4 v = *(const float4*)&x[(size_t)(row0 + r) * 256 + k0 + kq];
        As[kq+0][r] = v.x; As[kq+1][r] = v.y; As[kq+2][r] = v.z; As[kq+3][r] = v.w;
        float4 u = *(const float4*)&wm[(size_t)(o0 + r) * 256 + k0 + kq];
        Bs[kq+0][r] = u.x; Bs[kq+1][r] = u.y; Bs[kq+2][r] = u.z; Bs[kq+3][r] = u.w;
        __syncthreads();
        #pragma unroll
        for (int k = 0; k < 16; k++) {
            float4 a = *(float4*)&As[k][ty*4];
            float4 b = *(float4*)&Bs[k][tx*4];
            acc[0][0] += a.x*b.x; acc[0][1] += a.x*b.y; acc[0][2] += a.x*b.z; acc[0][3] += a.x*b.w;
            acc[1][0] += a.y*b.x; acc[1][1] += a.y*b.y; acc[1][2] += a.y*b.z; acc[1][3] += a.y*b.w;
            acc[2][0] += a.z*b.x; acc[2][1] += a.z*b.y; acc[2][2] += a.z*b.z; acc[2][3] += a.z*b.w;
            acc[3][0] += a.w*b.x; acc[3][1] += a.w*b.y; acc[3][2] += a.w*b.z; acc[3][3] += a.w*b.w;
        }
        __syncthreads();
    }
    if (tid < 64) scol[tid] = 0.f;
    __syncthreads();
    float cs[4] = {0,0,0,0};
    #pragma unroll
    for (int i = 0; i < 4; i++) {
        size_t base = (size_t)(row0 + ty*4 + i) * 256 + o0 + tx*4;
        float4 hv = *(const float4*)&g_hw[base];
        float4 cv;
        cv.x = acc[i][0]; cv.y = acc[i][1]; cv.z = acc[i][2]; cv.w = acc[i][3];
        *(float4*)&g_cc[base] = cv;
        cs[0] += hv.x + cv.x; cs[1] += hv.y + cv.y;
        cs[2] += hv.z + cv.z; cs[3] += hv.w + cv.w;
    }
    #pragma unroll
    for (int j = 0; j < 4; j++) atomicAdd(&scol[tx*4+j], cs[j]);
    __syncthreads();
    if (tid < 64) {
        int b = row0 / HWp;           // 64 | 3136 -> whole block is one image
        atomicAdd(&g_asum[b*256 + o0 + tid], scol[tid]);
    }
}

// ---------- tiny reweight MLP + pairwise softmax -> a0,a1 [16,256] ----------
__global__ __launch_bounds__(256) void k_small(const float* __restrict__ fc1w,
                                               const float* __restrict__ fc1b,
                                               const float* __restrict__ fc2w,
                                               const float* __restrict__ fc2b) {
    __shared__ float sm[16][256];
    __shared__ float sh1[16][64];
    int tid = threadIdx.x;
    const float inv = 1.0f / (float)HWp;
    for (int i = tid; i < 16*256; i += 256) sm[i >> 8][i & 255] = g_asum[i] * inv;
    __syncthreads();
    for (int idx = tid; idx < 16*64; idx += 256) {
        int b = idx >> 6, o = idx & 63;
        float a = fc1b[o];
        #pragma unroll 4
        for (int c = 0; c < 256; c++) a += sm[b][c] * fc1w[(size_t)o*256 + c];
        a = 0.5f * a * (1.0f + erff(a * 0.70710678118654752f));   // exact gelu
        sh1[b][o] = a;
    }
    __syncthreads();
    for (int idx = tid; idx < 16*256; idx += 256) {
        int b = idx >> 8, c = idx & 255;
        float l0 = fc2b[2*c], l1 = fc2b[2*c+1];
        #pragma unroll 4
        for (int k = 0; k < 64; k++) {
            float hv = sh1[b][k];
            l0 += hv * fc2w[(size_t)(2*c)*64 + k];
            l1 += hv * fc2w[(size_t)(2*c+1)*64 + k];
        }
        float m = fmaxf(l0, l1);
        float e0 = expf(l0 - m), e1 = expf(l1 - m);
        float s = 1.f / (e0 + e1);
        g_a0[idx] = e0 * s;
        g_a1[idx] = e1 * s;
    }
}

// ---------- final: y = hw*a0 + c*a1 ; out = y @ projcnn_w^T + b (A assembled on the fly) ----------
__global__ __launch_bounds__(256) void k_gemm_out(const float* __restrict__ wp,
                                                  const float* __restrict__ bp,
                                                  float* __restrict__ out) {
    __shared__ float As[16][64];
    __shared__ float Bs[16][64];
    __shared__ float sa0[256];
    __shared__ float sa1[256];
    int tid = threadIdx.x, tx = tid & 15, ty = tid >> 4;
    int row0 = blockIdx.x * 64, o0 = blockIdx.y * 64;
    int b = row0 / HWp;
    sa0[tid] = g_a0[b*256 + tid];
    sa1[tid] = g_a1[b*256 + tid];
    __syncthreads();
    float acc[4][4] = {};
    int r = tid >> 2, kq = (tid & 3) * 4;
    for (int k0 = 0; k0 < 256; k0 += 16) {
        size_t base = (size_t)(row0 + r) * 256 + k0 + kq;
        float4 hv = *(const float4*)&g_hw[base];
        float4 cv = *(const float4*)&g_cc[base];
        As[kq+0][r] = hv.x * sa0[k0+kq+0] + cv.x * sa1[k0+kq+0];
        As[kq+1][r] = hv.y * sa0[k0+kq+1] + cv.y * sa1[k0+kq+1];
        As[kq+2][r] = hv.z * sa0[k0+kq+2] + cv.z * sa1[k0+kq+2];
        As[kq+3][r] = hv.w * sa0[k0+kq+3] + cv.w * sa1[k0+kq+3];
        float4 u = *(const float4*)&wp[(size_t)(o0 + r) * 256 + k0 + kq];
        Bs[kq+0][r] = u.x; Bs[kq+1][r] = u.y; Bs[kq+2][r] = u.z; Bs[kq+3][r] = u.w;
        __syncthreads();
        #pragma unroll
        for (int k = 0; k < 16; k++) {
            float4 a = *(float4*)&As[k][ty*4];
            float4 bv = *(float4*)&Bs[k][tx*4];
            acc[0][0] += a.x*bv.x; acc[0][1] += a.x*bv.y; acc[0][2] += a.x*bv.z; acc[0][3] += a.x*bv.w;
            acc[1][0] += a.y*bv.x; acc[1][1] += a.y*bv.y; acc[1][2] += a.y*bv.z; acc[1][3] += a.y*bv.w;
            acc[2][0] += a.z*bv.x; acc[2][1] += a.z*bv.y; acc[2][2] += a.z*bv.z; acc[2][3] += a.z*bv.w;
            acc[3][0] += a.w*bv.x; acc[3][1] += a.w*bv.y; acc[3][2] += a.w*bv.z; acc[3][3] += a.w*bv.w;
        }
        __syncthreads();
    }
    float4 bb = *(const float4*)&bp[o0 + tx*4];
    #pragma unroll
    for (int i = 0; i < 4; i++) {
        size_t base = (size_t)(row0 + ty*4 + i) * 256 + o0 + tx*4;
        float4 vv;
        vv.x = acc[i][0] + bb.x; vv.y = acc[i][1] + bb.y;
        vv.z = acc[i][2] + bb.z; vv.w = acc[i][3] + bb.w;
        *(float4*)&out[base] = vv;
    }
}

extern "C" void kernel_launch(void* const* d_in, const int* in_sizes, int n_in,
                              void* d_out, int out_size) {
    const float* x        = (const float*)d_in[0];
    const float* conv1_w  = (const float*)d_in[1];
    const float* conv1_b  = (const float*)d_in[2];
    const float* bn_gamma = (const float*)d_in[3];
    const float* bn_beta  = (const float*)d_in[4];
    const float* conv2_w  = (const float*)d_in[5];
    const float* conv2_b  = (const float*)d_in[6];
    const float* mlp_c_w  = (const float*)d_in[7];
    const float* fc1_w    = (const float*)d_in[8];
    const float* fc1_b    = (const float*)d_in[9];
    const float* fc2_w    = (const float*)d_in[10];
    const float* fc2_b    = (const float*)d_in[11];
    const float* projcnn_w= (const float*)d_in[12];
    const float* projcnn_b= (const float*)d_in[13];
    float* out = (float*)d_out;

    k_zero<<<1, 256>>>();
    k_gemm1<<<Nn/64, 256>>>(x, conv1_w, conv1_b);
    k_kgen <<<Nn/64, 256>>>(bn_gamma, bn_beta, conv2_w, conv2_b);
    k_invo <<<Nn, 256>>>(x);
    dim3 g4(Nn/64, Cch/64);
    k_gemm_c<<<g4, 256>>>(x, mlp_c_w);
    k_small<<<1, 256>>>(fc1_w, fc1_b, fc2_w, fc2_b);
    k_gemm_out<<<g4, 256>>>(projcnn_w, projcnn_b, out);
}

// round 3
// speedup vs baseline: 1.3470x; 1.3470x over previous
#include <cuda_runtime.h>
#include <math.h>
#include <stdint.h>

#define Bc   16
#define Hh   56
#define Wd   56
#define Cch  256
#define C4c  64
#define GKK  72
#define HWp  (Hh*Wd)      // 3136
#define Nn   (Bc*HWp)     // 50176
#define EPSv 1e-5f

// ---- scratch (device globals) ----
__device__ float g_t[(size_t)Nn*C4c];
__device__ float g_wk[(size_t)Nn*GKK];
__device__ float g_hw[(size_t)Nn*Cch];
__device__ float g_cc[(size_t)Nn*Cch];
__device__ float g_sum[C4c];
__device__ float g_sumsq[C4c];
__device__ float g_asum[Bc*Cch];
__device__ float g_a0[Bc*Cch];
__device__ float g_a1[Bc*Cch];

// ================= helpers =================
__device__ __forceinline__ uint32_t f2tf(float f) {
    uint32_t r;
    asm("cvt.rna.tf32.f32 %0, %1;" : "=r"(r) : "f"(f));
    return r;
}
__device__ __forceinline__ float4 tf4(float4 v) {
    v.x = __uint_as_float(f2tf(v.x));
    v.y = __uint_as_float(f2tf(v.y));
    v.z = __uint_as_float(f2tf(v.z));
    v.w = __uint_as_float(f2tf(v.w));
    return v;
}
__device__ __forceinline__ void mma_t(float* c, const uint32_t* a, uint32_t b0, uint32_t b1) {
    asm volatile(
        "mma.sync.aligned.m16n8k8.row.col.f32.tf32.tf32.f32 "
        "{%0,%1,%2,%3}, {%4,%5,%6,%7}, {%8,%9}, {%0,%1,%2,%3};"
        : "+f"(c[0]), "+f"(c[1]), "+f"(c[2]), "+f"(c[3])
        : "r"(a[0]), "r"(a[1]), "r"(a[2]), "r"(a[3]), "r"(b0), "r"(b1));
}
#define SA 36   // smem row stride (floats): makes fragment LDS conflict-free

// ============================ kernels ============================

__global__ void k_zero() {
    int tid = threadIdx.x;
    if (tid < C4c) { g_sum[tid] = 0.f; g_sumsq[tid] = 0.f; }
    for (int i = tid; i < Bc*Cch; i += 256) g_asum[i] = 0.f;
}

// ---------- GEMM1: t[N,64] = tf32mma( x[N,256] @ conv1_w[64,256]^T ) + b ; BN stats ----------
__global__ __launch_bounds__(256) void k_mma_g1(const float* __restrict__ x,
                                                const float* __restrict__ w1,
                                                const float* __restrict__ b1) {
    __shared__ float As[128*SA];
    __shared__ float Bs[64*SA];
    __shared__ float scol[64], ssq[64];
    int tid = threadIdx.x, wid = tid >> 5, lane = tid & 31;
    int lr = lane >> 2, lc = lane & 3;
    int wm = wid & 3, wn = wid >> 2;        // 4 x 2 warps, warp tile 32x32
    int row0 = blockIdx.x * 128;
    if (tid < 64) { scol[tid] = 0.f; ssq[tid] = 0.f; }

    float acc[2][4][4] = {};
    float4 fa[4], fb[2];
    #pragma unroll
    for (int t = 0; t < 4; t++) { int idx = tid + t*256, r = idx >> 3, j = idx & 7;
        fa[t] = *(const float4*)&x[(size_t)(row0 + r)*256 + j*4]; }
    #pragma unroll
    for (int t = 0; t < 2; t++) { int idx = tid + t*256, r = idx >> 3, j = idx & 7;
        fb[t] = *(const float4*)&w1[(size_t)r*256 + j*4]; }

    for (int ch = 0; ch < 8; ch++) {
        if (ch) __syncthreads();
        #pragma unroll
        for (int t = 0; t < 4; t++) { int idx = tid + t*256, r = idx >> 3, j = idx & 7;
            *(float4*)&As[r*SA + j*4] = tf4(fa[t]); }
        #pragma unroll
        for (int t = 0; t < 2; t++) { int idx = tid + t*256, r = idx >> 3, j = idx & 7;
            *(float4*)&Bs[r*SA + j*4] = tf4(fb[t]); }
        __syncthreads();
        if (ch < 7) {
            int k0 = (ch + 1) * 32;
            #pragma unroll
            for (int t = 0; t < 4; t++) { int idx = tid + t*256, r = idx >> 3, j = idx & 7;
                fa[t] = *(const float4*)&x[(size_t)(row0 + r)*256 + k0 + j*4]; }
            #pragma unroll
            for (int t = 0; t < 2; t++) { int idx = tid + t*256, r = idx >> 3, j = idx & 7;
                fb[t] = *(const float4*)&w1[(size_t)r*256 + k0 + j*4]; }
        }
        #pragma unroll
        for (int s = 0; s < 4; s++) {
            uint32_t a[2][4];
            #pragma unroll
            for (int mi = 0; mi < 2; mi++) {
                const float* Ap = &As[(wm*32 + mi*16 + lr)*SA + s*8 + lc];
                a[mi][0] = __float_as_uint(Ap[0]);
                a[mi][1] = __float_as_uint(Ap[8*SA]);
                a[mi][2] = __float_as_uint(Ap[4]);
                a[mi][3] = __float_as_uint(Ap[8*SA + 4]);
            }
            #pragma unroll
            for (int nj = 0; nj < 4; nj++) {
                const float* Bp = &Bs[(wn*32 + nj*8 + lr)*SA + s*8 + lc];
                uint32_t b0 = __float_as_uint(Bp[0]);
                uint32_t b1 = __float_as_uint(Bp[4]);
                mma_t(acc[0][nj], a[0], b0, b1);
                mma_t(acc[1][nj], a[1], b0, b1);
            }
        }
    }
    __syncthreads();

    // epilogue: +bias, write g_t, BN stats
    #pragma unroll
    for (int nj = 0; nj < 4; nj++) {
        int c0 = wn*32 + nj*8 + lc*2;
        float bb0 = __ldg(&b1[c0]), bb1 = __ldg(&b1[c0+1]);
        float s0 = 0.f, s1 = 0.f, q0 = 0.f, q1 = 0.f;
        #pragma unroll
        for (int mi = 0; mi < 2; mi++) {
            int row = row0 + wm*32 + mi*16 + lr;
            float v0 = acc[mi][nj][0] + bb0;
            float v1 = acc[mi][nj][1] + bb1;
            float v2 = acc[mi][nj][2] + bb0;
            float v3 = acc[mi][nj][3] + bb1;
            *(float2*)&g_t[(size_t)row*64 + c0]     = make_float2(v0, v1);
            *(float2*)&g_t[(size_t)(row+8)*64 + c0] = make_float2(v2, v3);
            s0 += v0 + v2; s1 += v1 + v3;
            q0 += v0*v0 + v2*v2; q1 += v1*v1 + v3*v3;
        }
        atomicAdd(&scol[c0], s0);   atomicAdd(&scol[c0+1], s1);
        atomicAdd(&ssq[c0],  q0);   atomicAdd(&ssq[c0+1],  q1);
    }
    __syncthreads();
    if (tid < 64) {
        atomicAdd(&g_sum[tid],   scol[tid]);
        atomicAdd(&g_sumsq[tid], ssq[tid]);
    }
}

// ---------- BN + relu + kernel-gen GEMM (FFMA, small) ----------
__global__ __launch_bounds__(256) void k_kgen(const float* __restrict__ gamma,
                                              const float* __restrict__ beta,
                                              const float* __restrict__ w2,
                                              const float* __restrict__ b2) {
    __shared__ float ts[64][65];
    __shared__ float ws[72][65];
    int tid = threadIdx.x;
    int row0 = blockIdx.x * 64;
    for (int idx = tid; idx < 72*64; idx += 256) {
        int o = idx / 64, k = idx % 64;
        ws[o][k] = w2[idx];
    }
    const float invN = 1.0f / (float)Nn;
    for (int idx = tid; idx < 64*64; idx += 256) {
        int r = idx >> 6, ch = idx & 63;
        float mu  = g_sum[ch] * invN;
        float var = g_sumsq[ch] * invN - mu * mu;
        float v = g_t[(size_t)(row0 + r) * 64 + ch];
        v = gamma[ch] * (v - mu) * rsqrtf(var + EPSv) + beta[ch];
        ts[r][ch] = fmaxf(v, 0.f);
    }
    __syncthreads();
    #pragma unroll 2
    for (int j = 0; j < 18; j++) {
        int idx = tid + j * 256;
        int r = idx / 72, o = idx % 72;
        float acc = 0.f;
        #pragma unroll
        for (int k = 0; k < 64; k++) acc += ts[r][k] * ws[o][k];
        g_wk[(size_t)(row0 + r) * 72 + o] = acc + b2[o];
    }
}

// ---------- involution ----------
__global__ __launch_bounds__(256) void k_invo(const float* __restrict__ x) {
    __shared__ float wsh[72];
    int n = blockIdx.x;
    int tid = threadIdx.x;
    if (tid < 72) wsh[tid] = g_wk[(size_t)n * 72 + tid];
    __syncthreads();
    int b = n / HWp, hw = n % HWp, h = hw / Wd, w = hw % Wd;
    int g9 = (tid >> 5) * 9;
    float acc = 0.f;
    #pragma unroll
    for (int dy = -1; dy <= 1; dy++) {
        int hh = h + dy;
        if (hh < 0 || hh >= Hh) continue;
        #pragma unroll
        for (int dx = -1; dx <= 1; dx++) {
            int ww = w + dx;
            if (ww < 0 || ww >= Wd) continue;
            acc += wsh[g9 + (dy+1)*3 + (dx+1)] *
                   __ldg(&x[((size_t)(b*Hh + hh)*Wd + ww)*256 + tid]);
        }
    }
    g_hw[(size_t)n * 256 + tid] = acc;
}

// ---------- GEMM c = tf32mma( x @ mlp_c_w^T ), N tile 128 ----------
__global__ __launch_bounds__(256) void k_mma_c(const float* __restrict__ x,
                                               const float* __restrict__ wm_) {
    __shared__ float As[128*SA];
    __shared__ float Bs[128*SA];
    int tid = threadIdx.x, wid = tid >> 5, lane = tid & 31;
    int lr = lane >> 2, lc = lane & 3;
    int wm = wid & 3, wn = wid >> 2;        // warp tile 32x64
    int row0 = blockIdx.x * 128, col0 = blockIdx.y * 128;

    float acc[2][8][4] = {};
    float4 fa[4], fb[4];
    #pragma unroll
    for (int t = 0; t < 4; t++) { int idx = tid + t*256, r = idx >> 3, j = idx & 7;
        fa[t] = *(const float4*)&x[(size_t)(row0 + r)*256 + j*4];
        fb[t] = *(const float4*)&wm_[(size_t)(col0 + r)*256 + j*4]; }

    for (int ch = 0; ch < 8; ch++) {
        if (ch) __syncthreads();
        #pragma unroll
        for (int t = 0; t < 4; t++) { int idx = tid + t*256, r = idx >> 3, j = idx & 7;
            *(float4*)&As[r*SA + j*4] = tf4(fa[t]);
            *(float4*)&Bs[r*SA + j*4] = tf4(fb[t]); }
        __syncthreads();
        if (ch < 7) {
            int k0 = (ch + 1) * 32;
            #pragma unroll
            for (int t = 0; t < 4; t++) { int idx = tid + t*256, r = idx >> 3, j = idx & 7;
                fa[t] = *(const float4*)&x[(size_t)(row0 + r)*256 + k0 + j*4];
                fb[t] = *(const float4*)&wm_[(size_t)(col0 + r)*256 + k0 + j*4]; }
        }
        #pragma unroll
        for (int s = 0; s < 4; s++) {
            uint32_t a[2][4];
            #pragma unroll
            for (int mi = 0; mi < 2; mi++) {
                const float* Ap = &As[(wm*32 + mi*16 + lr)*SA + s*8 + lc];
                a[mi][0] = __float_as_uint(Ap[0]);
                a[mi][1] = __float_as_uint(Ap[8*SA]);
                a[mi][2] = __float_as_uint(Ap[4]);
                a[mi][3] = __float_as_uint(Ap[8*SA + 4]);
            }
            #pragma unroll
            for (int nj = 0; nj < 8; nj++) {
                const float* Bp = &Bs[(wn*64 + nj*8 + lr)*SA + s*8 + lc];
                uint32_t b0 = __float_as_uint(Bp[0]);
                uint32_t b1 = __float_as_uint(Bp[4]);
                mma_t(acc[0][nj], a[0], b0, b1);
                mma_t(acc[1][nj], a[1], b0, b1);
            }
        }
    }

    #pragma unroll
    for (int mi = 0; mi < 2; mi++) {
        int row = row0 + wm*32 + mi*16 + lr;
        #pragma unroll
        for (int nj = 0; nj < 8; nj++) {
            int col = col0 + wn*64 + nj*8 + lc*2;
            *(float2*)&g_cc[(size_t)row*256 + col]     = make_float2(acc[mi][nj][0], acc[mi][nj][1]);
            *(float2*)&g_cc[(size_t)(row+8)*256 + col] = make_float2(acc[mi][nj][2], acc[mi][nj][3]);
        }
    }
}

// ---------- spatial-mean reduction ----------
__global__ __launch_bounds__(256) void k_mean() {
    int tid = threadIdx.x;
    int row0 = blockIdx.x * 128;
    int col = tid;
    float acc = 0.f;
    int curb = row0 / HWp;
    for (int r = 0; r < 128; r++) {
        int row = row0 + r;
        int b = row / HWp;
        if (b != curb) { atomicAdd(&g_asum[curb*256 + col], acc); acc = 0.f; curb = b; }
        acc += g_hw[(size_t)row*256 + col] + g_cc[(size_t)row*256 + col];
    }
    atomicAdd(&g_asum[curb*256 + col], acc);
}

// ---------- tiny reweight MLP + pairwise softmax ----------
__global__ __launch_bounds__(256) void k_small(const float* __restrict__ fc1w,
                                               const float* __restrict__ fc1b,
                                               const float* __restrict__ fc2w,
                                               const float* __restrict__ fc2b) {
    __shared__ float sm[16][256];
    __shared__ float sh1[16][64];
    int tid = threadIdx.x;
    const float inv = 1.0f / (float)HWp;
    for (int i = tid; i < 16*256; i += 256) sm[i >> 8][i & 255] = g_asum[i] * inv;
    __syncthreads();
    for (int idx = tid; idx < 16*64; idx += 256) {
        int b = idx >> 6, o = idx & 63;
        float a = fc1b[o];
        #pragma unroll 4
        for (int c = 0; c < 256; c++) a += sm[b][c] * fc1w[(size_t)o*256 + c];
        a = 0.5f * a * (1.0f + erff(a * 0.70710678118654752f));
        sh1[b][o] = a;
    }
    __syncthreads();
    for (int idx = tid; idx < 16*256; idx += 256) {
        int b = idx >> 8, c = idx & 255;
        float l0 = fc2b[2*c], l1 = fc2b[2*c+1];
        #pragma unroll 4
        for (int k = 0; k < 64; k++) {
            float hv = sh1[b][k];
            l0 += hv * fc2w[(size_t)(2*c)*64 + k];
            l1 += hv * fc2w[(size_t)(2*c+1)*64 + k];
        }
        float m = fmaxf(l0, l1);
        float e0 = expf(l0 - m), e1 = expf(l1 - m);
        float s = 1.f / (e0 + e1);
        g_a0[idx] = e0 * s;
        g_a1[idx] = e1 * s;
    }
}

// ---------- final GEMM: out = tf32mma( (hw*a0 + c*a1) @ projcnn_w^T ) + b ----------
__global__ __launch_bounds__(256) void k_mma_out(const float* __restrict__ wp,
                                                 const float* __restrict__ bp,
                                                 float* __restrict__ out) {
    __shared__ float As[128*SA];
    __shared__ float Bs[128*SA];
    int tid = threadIdx.x, wid = tid >> 5, lane = tid & 31;
    int lr = lane >> 2, lc = lane & 3;
    int wm = wid & 3, wn = wid >> 2;
    int row0 = blockIdx.x * 128, col0 = blockIdx.y * 128;

    float acc[2][8][4] = {};
    float4 fh[4], fc4[4], fb[4];
    #pragma unroll
    for (int t = 0; t < 4; t++) { int idx = tid + t*256, r = idx >> 3, j = idx & 7;
        size_t p = (size_t)(row0 + r)*256 + j*4;
        fh[t]  = *(const float4*)&g_hw[p];
        fc4[t] = *(const float4*)&g_cc[p];
        fb[t]  = *(const float4*)&wp[(size_t)(col0 + r)*256 + j*4]; }

    for (int ch = 0; ch < 8; ch++) {
        if (ch) __syncthreads();
        int k0 = ch * 32;
        #pragma unroll
        for (int t = 0; t < 4; t++) {
            int idx = tid + t*256, r = idx >> 3, j = idx & 7;
            int b = (row0 + r) / HWp;
            const float* pa0 = &g_a0[b*256 + k0 + j*4];
            const float* pa1 = &g_a1[b*256 + k0 + j*4];
            float4 v;
            v.x = fh[t].x * __ldg(&pa0[0]) + fc4[t].x * __ldg(&pa1[0]);
            v.y = fh[t].y * __ldg(&pa0[1]) + fc4[t].y * __ldg(&pa1[1]);
            v.z = fh[t].z * __ldg(&pa0[2]) + fc4[t].z * __ldg(&pa1[2]);
            v.w = fh[t].w * __ldg(&pa0[3]) + fc4[t].w * __ldg(&pa1[3]);
            *(float4*)&As[r*SA + j*4] = tf4(v);
            *(float4*)&Bs[r*SA + j*4] = tf4(fb[t]);
        }
        __syncthreads();
        if (ch < 7) {
            int k1 = (ch + 1) * 32;
            #pragma unroll
            for (int t = 0; t < 4; t++) { int idx = tid + t*256, r = idx >> 3, j = idx & 7;
                size_t p = (size_t)(row0 + r)*256 + k1 + j*4;
                fh[t]  = *(const float4*)&g_hw[p];
                fc4[t] = *(const float4*)&g_cc[p];
                fb[t]  = *(const float4*)&wp[(size_t)(col0 + r)*256 + k1 + j*4]; }
        }
        #pragma unroll
        for (int s = 0; s < 4; s++) {
            uint32_t a[2][4];
            #pragma unroll
            for (int mi = 0; mi < 2; mi++) {
                const float* Ap = &As[(wm*32 + mi*16 + lr)*SA + s*8 + lc];
                a[mi][0] = __float_as_uint(Ap[0]);
                a[mi][1] = __float_as_uint(Ap[8*SA]);
                a[mi][2] = __float_as_uint(Ap[4]);
                a[mi][3] = __float_as_uint(Ap[8*SA + 4]);
            }
            #pragma unroll
            for (int nj = 0; nj < 8; nj++) {
                const float* Bp = &Bs[(wn*64 + nj*8 + lr)*SA + s*8 + lc];
                uint32_t b0 = __float_as_uint(Bp[0]);
                uint32_t b1 = __float_as_uint(Bp[4]);
                mma_t(acc[0][nj], a[0], b0, b1);
                mma_t(acc[1][nj], a[1], b0, b1);
            }
        }
    }

    #pragma unroll
    for (int mi = 0; mi < 2; mi++) {
        int row = row0 + wm*32 + mi*16 + lr;
        #pragma unroll
        for (int nj = 0; nj < 8; nj++) {
            int col = col0 + wn*64 + nj*8 + lc*2;
            float bb0 = __ldg(&bp[col]), bb1 = __ldg(&bp[col+1]);
            *(float2*)&out[(size_t)row*256 + col] =
                make_float2(acc[mi][nj][0] + bb0, acc[mi][nj][1] + bb1);
            *(float2*)&out[(size_t)(row+8)*256 + col] =
                make_float2(acc[mi][nj][2] + bb0, acc[mi][nj][3] + bb1);
        }
    }
}

extern "C" void kernel_launch(void* const* d_in, const int* in_sizes, int n_in,
                              void* d_out, int out_size) {
    const float* x        = (const float*)d_in[0];
    const float* conv1_w  = (const float*)d_in[1];
    const float* conv1_b  = (const float*)d_in[2];
    const float* bn_gamma = (const float*)d_in[3];
    const float* bn_beta  = (const float*)d_in[4];
    const float* conv2_w  = (const float*)d_in[5];
    const float* conv2_b  = (const float*)d_in[6];
    const float* mlp_c_w  = (const float*)d_in[7];
    const float* fc1_w    = (const float*)d_in[8];
    const float* fc1_b    = (const float*)d_in[9];
    const float* fc2_w    = (const float*)d_in[10];
    const float* fc2_b    = (const float*)d_in[11];
    const float* projcnn_w= (const float*)d_in[12];
    const float* projcnn_b= (const float*)d_in[13];
    float* out = (float*)d_out;

    k_zero<<<1, 256>>>();
    k_mma_g1<<<Nn/128, 256>>>(x, conv1_w, conv1_b);
    k_kgen  <<<Nn/64, 256>>>(bn_gamma, bn_beta, conv2_w, conv2_b);
    k_invo  <<<Nn, 256>>>(x);
    dim3 g2(Nn/128, Cch/128);
    k_mma_c <<<g2, 256>>>(x, mlp_c_w);
    k_mean  <<<Nn/128, 256>>>();
    k_small <<<1, 256>>>(fc1_w, fc1_b, fc2_w, fc2_b);
    k_mma_out<<<g2, 256>>>(projcnn_w, projcnn_b, out);
}

// round 4
// speedup vs baseline: 1.5945x; 1.1838x over previous
#include <cuda_runtime.h>
#include <math.h>
#include <stdint.h>

#define Bc   16
#define Hh   56
#define Wd   56
#define Cch  256
#define C4c  64
#define GKK  72
#define HWp  (Hh*Wd)      // 3136
#define Nn   (Bc*HWp)     // 50176
#define EPSv 1e-5f

// ---- scratch (device globals) ----
__device__ float g_t[(size_t)Nn*C4c];
__device__ float g_wk[(size_t)Nn*GKK];
__device__ float g_hw[(size_t)Nn*Cch];
__device__ float g_cc[(size_t)Nn*Cch];
__device__ float g_sum[C4c];
__device__ float g_sumsq[C4c];
__device__ float g_asum[Bc*Cch];
__device__ float g_a0[Bc*Cch];
__device__ float g_a1[Bc*Cch];

// ================= helpers =================
__device__ __forceinline__ uint32_t f2tf(float f) {
    uint32_t r;
    asm("cvt.rna.tf32.f32 %0, %1;" : "=r"(r) : "f"(f));
    return r;
}
__device__ __forceinline__ float4 tf4(float4 v) {
    v.x = __uint_as_float(f2tf(v.x));
    v.y = __uint_as_float(f2tf(v.y));
    v.z = __uint_as_float(f2tf(v.z));
    v.w = __uint_as_float(f2tf(v.w));
    return v;
}
__device__ __forceinline__ void mma_t(float* c, const uint32_t* a, uint32_t b0, uint32_t b1) {
    asm volatile(
        "mma.sync.aligned.m16n8k8.row.col.f32.tf32.tf32.f32 "
        "{%0,%1,%2,%3}, {%4,%5,%6,%7}, {%8,%9}, {%0,%1,%2,%3};"
        : "+f"(c[0]), "+f"(c[1]), "+f"(c[2]), "+f"(c[3])
        : "r"(a[0]), "r"(a[1]), "r"(a[2]), "r"(a[3]), "r"(b0), "r"(b1));
}
#define SA 36         // smem row stride (floats)
#define BUF 9216      // per-parity buffer floats: A 128*36=4608, B 128*36=4608

// ============================ kernels ============================

__global__ void k_zero() {
    int tid = threadIdx.x;
    if (tid < C4c) { g_sum[tid] = 0.f; g_sumsq[tid] = 0.f; }
    for (int i = tid; i < Bc*Cch; i += 256) g_asum[i] = 0.f;
}

// ---------- GEMM1: t = x @ conv1_w^T + b ; fused BN stats (known-good from R3) ----------
__global__ __launch_bounds__(256) void k_mma_g1(const float* __restrict__ x,
                                                const float* __restrict__ w1,
                                                const float* __restrict__ b1) {
    __shared__ float As[128*SA];
    __shared__ float Bs[64*SA];
    __shared__ float scol[64], ssq[64];
    int tid = threadIdx.x, wid = tid >> 5, lane = tid & 31;
    int lr = lane >> 2, lc = lane & 3;
    int wm = wid & 3, wn = wid >> 2;
    int row0 = blockIdx.x * 128;
    if (tid < 64) { scol[tid] = 0.f; ssq[tid] = 0.f; }

    float acc[2][4][4] = {};
    float4 fa[4], fb[2];
    #pragma unroll
    for (int t = 0; t < 4; t++) { int idx = tid + t*256, r = idx >> 3, j = idx & 7;
        fa[t] = *(const float4*)&x[(size_t)(row0 + r)*256 + j*4]; }
    #pragma unroll
    for (int t = 0; t < 2; t++) { int idx = tid + t*256, r = idx >> 3, j = idx & 7;
        fb[t] = *(const float4*)&w1[(size_t)r*256 + j*4]; }

    for (int ch = 0; ch < 8; ch++) {
        if (ch) __syncthreads();
        #pragma unroll
        for (int t = 0; t < 4; t++) { int idx = tid + t*256, r = idx >> 3, j = idx & 7;
            *(float4*)&As[r*SA + j*4] = tf4(fa[t]); }
        #pragma unroll
        for (int t = 0; t < 2; t++) { int idx = tid + t*256, r = idx >> 3, j = idx & 7;
            *(float4*)&Bs[r*SA + j*4] = tf4(fb[t]); }
        __syncthreads();
        if (ch < 7) {
            int k0 = (ch + 1) * 32;
            #pragma unroll
            for (int t = 0; t < 4; t++) { int idx = tid + t*256, r = idx >> 3, j = idx & 7;
                fa[t] = *(const float4*)&x[(size_t)(row0 + r)*256 + k0 + j*4]; }
            #pragma unroll
            for (int t = 0; t < 2; t++) { int idx = tid + t*256, r = idx >> 3, j = idx & 7;
                fb[t] = *(const float4*)&w1[(size_t)r*256 + k0 + j*4]; }
        }
        #pragma unroll
        for (int s = 0; s < 4; s++) {
            uint32_t a[2][4];
            #pragma unroll
            for (int mi = 0; mi < 2; mi++) {
                const float* Ap = &As[(wm*32 + mi*16 + lr)*SA + s*8 + lc];
                a[mi][0] = __float_as_uint(Ap[0]);
                a[mi][1] = __float_as_uint(Ap[8*SA]);
                a[mi][2] = __float_as_uint(Ap[4]);
                a[mi][3] = __float_as_uint(Ap[8*SA + 4]);
            }
            #pragma unroll
            for (int nj = 0; nj < 4; nj++) {
                const float* Bp = &Bs[(wn*32 + nj*8 + lr)*SA + s*8 + lc];
                uint32_t b0 = __float_as_uint(Bp[0]);
                uint32_t b1 = __float_as_uint(Bp[4]);
                mma_t(acc[0][nj], a[0], b0, b1);
                mma_t(acc[1][nj], a[1], b0, b1);
            }
        }
    }
    __syncthreads();

    #pragma unroll
    for (int nj = 0; nj < 4; nj++) {
        int c0 = wn*32 + nj*8 + lc*2;
        float bb0 = __ldg(&b1[c0]), bb1 = __ldg(&b1[c0+1]);
        float s0 = 0.f, s1 = 0.f, q0 = 0.f, q1 = 0.f;
        #pragma unroll
        for (int mi = 0; mi < 2; mi++) {
            int row = row0 + wm*32 + mi*16 + lr;
            float v0 = acc[mi][nj][0] + bb0;
            float v1 = acc[mi][nj][1] + bb1;
            float v2 = acc[mi][nj][2] + bb0;
            float v3 = acc[mi][nj][3] + bb1;
            *(float2*)&g_t[(size_t)row*64 + c0]     = make_float2(v0, v1);
            *(float2*)&g_t[(size_t)(row+8)*64 + c0] = make_float2(v2, v3);
            s0 += v0 + v2; s1 += v1 + v3;
            q0 += v0*v0 + v2*v2; q1 += v1*v1 + v3*v3;
        }
        atomicAdd(&scol[c0], s0);   atomicAdd(&scol[c0+1], s1);
        atomicAdd(&ssq[c0],  q0);   atomicAdd(&ssq[c0+1],  q1);
    }
    __syncthreads();
    if (tid < 64) {
        atomicAdd(&g_sum[tid],   scol[tid]);
        atomicAdd(&g_sumsq[tid], ssq[tid]);
    }
}

// ---------- kernel-gen (tf32 MMA): wk[N,72] = relu(bn(t)) @ conv2_w^T + b ----------
__global__ __launch_bounds__(256) void k_mma_kg(const float* __restrict__ gamma,
                                                const float* __restrict__ beta,
                                                const float* __restrict__ w2,
                                                const float* __restrict__ b2) {
    __shared__ float As[128*SA];
    __shared__ float Bs[80*SA];
    __shared__ float sc[64], shf[64];
    int tid = threadIdx.x, wid = tid >> 5, lane = tid & 31;
    int lr = lane >> 2, lc = lane & 3;
    int wm = wid & 3, wn = wid >> 2;          // 4 x 2 warps, warp tile 32x40
    int row0 = blockIdx.x * 128;
    if (tid < 64) {
        const float invN = 1.0f / (float)Nn;
        float mu  = g_sum[tid] * invN;
        float var = g_sumsq[tid] * invN - mu * mu;
        float s = gamma[tid] * rsqrtf(var + EPSv);
        sc[tid]  = s;
        shf[tid] = beta[tid] - mu * s;
    }
    __syncthreads();

    float acc[2][5][4] = {};
    for (int ch = 0; ch < 2; ch++) {
        if (ch) __syncthreads();
        #pragma unroll
        for (int t = 0; t < 4; t++) {
            int idx = tid + t*256, r = idx >> 3, j = idx & 7;
            int c = ch*32 + j*4;
            float4 v = *(const float4*)&g_t[(size_t)(row0 + r)*64 + c];
            v.x = fmaxf(fmaf(v.x, sc[c+0], shf[c+0]), 0.f);
            v.y = fmaxf(fmaf(v.y, sc[c+1], shf[c+1]), 0.f);
            v.z = fmaxf(fmaf(v.z, sc[c+2], shf[c+2]), 0.f);
            v.w = fmaxf(fmaf(v.w, sc[c+3], shf[c+3]), 0.f);
            *(float4*)&As[r*SA + j*4] = tf4(v);
        }
        for (int idx = tid; idx < 80*8; idx += 256) {
            int r = idx >> 3, j = idx & 7;
            float4 v = make_float4(0.f, 0.f, 0.f, 0.f);
            if (r < 72) v = *(const float4*)&w2[(size_t)r*64 + ch*32 + j*4];
            *(float4*)&Bs[r*SA + j*4] = tf4(v);
        }
        __syncthreads();
        #pragma unroll
        for (int s = 0; s < 4; s++) {
            uint32_t a[2][4];
            #pragma unroll
            for (int mi = 0; mi < 2; mi++) {
                const float* Ap = &As[(wm*32 + mi*16 + lr)*SA + s*8 + lc];
                a[mi][0] = __float_as_uint(Ap[0]);
                a[mi][1] = __float_as_uint(Ap[8*SA]);
                a[mi][2] = __float_as_uint(Ap[4]);
                a[mi][3] = __float_as_uint(Ap[8*SA + 4]);
            }
            #pragma unroll
            for (int nj = 0; nj < 5; nj++) {
                const float* Bp = &Bs[(wn*40 + nj*8 + lr)*SA + s*8 + lc];
                uint32_t b0 = __float_as_uint(Bp[0]);
                uint32_t b1 = __float_as_uint(Bp[4]);
                mma_t(acc[0][nj], a[0], b0, b1);
                mma_t(acc[1][nj], a[1], b0, b1);
            }
        }
    }

    #pragma unroll
    for (int mi = 0; mi < 2; mi++) {
        int row = row0 + wm*32 + mi*16 + lr;
        #pragma unroll
        for (int nj = 0; nj < 5; nj++) {
            int col = wn*40 + nj*8 + lc*2;
            if (col < 72) {
                float bb0 = __ldg(&b2[col]), bb1 = __ldg(&b2[col+1]);
                *(float2*)&g_wk[(size_t)row*72 + col] =
                    make_float2(acc[mi][nj][0] + bb0, acc[mi][nj][1] + bb1);
                *(float2*)&g_wk[(size_t)(row+8)*72 + col] =
                    make_float2(acc[mi][nj][2] + bb0, acc[mi][nj][3] + bb1);
            }
        }
    }
}

// ---------- involution (row-tiled): grid (Bc*Hh, 8 groups), block 256 ----------
__global__ __launch_bounds__(256) void k_invo2(const float* __restrict__ x) {
    __shared__ float xs[3][58][32];    // padded w columns 0 and 57 are zero
    __shared__ float ws[56][9];
    int bh = blockIdx.x;               // b*Hh + h
    int g  = blockIdx.y;               // group / 32-channel slice
    int b = bh / Hh, h = bh % Hh;
    int tid = threadIdx.x;

    if (tid < 192) {
        int dy = tid / 64, e = (tid >> 5) & 1, c = tid & 31;
        xs[dy][e ? 57 : 0][c] = 0.f;
    }
    for (int i = tid; i < 3*56*8; i += 256) {         // 1344 float4
        int c4 = i & 7, w = (i >> 3) % 56, dy = i / 448;
        int hh = h + dy - 1;
        float4 v = make_float4(0.f, 0.f, 0.f, 0.f);
        if (hh >= 0 && hh < Hh)
            v = *(const float4*)&x[(((size_t)(b*Hh + hh))*Wd + w)*256 + g*32 + c4*4];
        *(float4*)&xs[dy][1 + w][c4*4] = v;
    }
    for (int i = tid; i < 56*9; i += 256) {
        int w = i / 9, k = i % 9;
        ws[w][k] = g_wk[((size_t)bh*Wd + w)*72 + g*9 + k];
    }
    __syncthreads();

    int c = tid & 31, wq = tid >> 5;
    #pragma unroll
    for (int i = 0; i < 7; i++) {
        int w = wq + i*8;
        float acc = 0.f;
        #pragma unroll
        for (int dy = 0; dy < 3; dy++)
            #pragma unroll
            for (int dx = 0; dx < 3; dx++)
                acc += ws[w][dy*3 + dx] * xs[dy][w + dx][c];
        g_hw[(((size_t)bh)*Wd + w)*256 + g*32 + c] = acc;
    }
}

// ---------- GEMM c = x @ mlp_c_w^T  (double-buffered, fused (hw+c) mean) ----------
__global__ __launch_bounds__(256) void k_mma_c(const float* __restrict__ x,
                                               const float* __restrict__ wmw) {
    extern __shared__ float dsm[];
    __shared__ float scol[2][128];
    int tid = threadIdx.x, wid = tid >> 5, lane = tid & 31;
    int lr = lane >> 2, lc = lane & 3;
    int wm = wid & 3, wn = wid >> 2;
    int row0 = blockIdx.x * 128, col0 = blockIdx.y * 128;
    if (tid < 128) { scol[0][tid] = 0.f; scol[1][tid] = 0.f; }

    float acc[2][8][4] = {};
    float4 fa[4], fb[4];
    #pragma unroll
    for (int t = 0; t < 4; t++) { int idx = tid + t*256, r = idx >> 3, j = idx & 7;
        fa[t] = *(const float4*)&x[(size_t)(row0 + r)*256 + j*4];
        fb[t] = *(const float4*)&wmw[(size_t)(col0 + r)*256 + j*4]; }
    #pragma unroll
    for (int t = 0; t < 4; t++) { int idx = tid + t*256, r = idx >> 3, j = idx & 7;
        *(float4*)&dsm[r*SA + j*4]        = tf4(fa[t]);
        *(float4*)&dsm[4608 + r*SA + j*4] = tf4(fb[t]); }
    __syncthreads();

    for (int ch = 0; ch < 8; ch++) {
        int p = ch & 1, q = p ^ 1;
        if (ch < 7) {
            int k0 = (ch + 1) * 32;
            #pragma unroll
            for (int t = 0; t < 4; t++) { int idx = tid + t*256, r = idx >> 3, j = idx & 7;
                fa[t] = *(const float4*)&x[(size_t)(row0 + r)*256 + k0 + j*4];
                fb[t] = *(const float4*)&wmw[(size_t)(col0 + r)*256 + k0 + j*4]; }
        }
        const float* Ab = &dsm[p*BUF];
        const float* Bb = &dsm[p*BUF + 4608];
        #pragma unroll
        for (int s = 0; s < 4; s++) {
            uint32_t a[2][4];
            #pragma unroll
            for (int mi = 0; mi < 2; mi++) {
                const float* Ap = &Ab[(wm*32 + mi*16 + lr)*SA + s*8 + lc];
                a[mi][0] = __float_as_uint(Ap[0]);
                a[mi][1] = __float_as_uint(Ap[8*SA]);
                a[mi][2] = __float_as_uint(Ap[4]);
                a[mi][3] = __float_as_uint(Ap[8*SA + 4]);
            }
            #pragma unroll
            for (int nj = 0; nj < 8; nj++) {
                const float* Bp = &Bb[(wn*64 + nj*8 + lr)*SA + s*8 + lc];
                uint32_t b0 = __float_as_uint(Bp[0]);
                uint32_t b1 = __float_as_uint(Bp[4]);
                mma_t(acc[0][nj], a[0], b0, b1);
                mma_t(acc[1][nj], a[1], b0, b1);
            }
        }
        if (ch < 7) {
            #pragma unroll
            for (int t = 0; t < 4; t++) { int idx = tid + t*256, r = idx >> 3, j = idx & 7;
                *(float4*)&dsm[q*BUF + r*SA + j*4]        = tf4(fa[t]);
                *(float4*)&dsm[q*BUF + 4608 + r*SA + j*4] = tf4(fb[t]); }
        }
        __syncthreads();
    }

    // epilogue: write cc, accumulate (hw + cc) column sums split by image
    int bimg = row0 / HWp;
    int bsplit = (bimg + 1) * HWp;
    #pragma unroll
    for (int nj = 0; nj < 8; nj++) {
        int colr = wn*64 + nj*8 + lc*2;
        int col = col0 + colr;
        float s0[2] = {0.f, 0.f}, s1[2] = {0.f, 0.f};
        #pragma unroll
        for (int mi = 0; mi < 2; mi++) {
            int row = row0 + wm*32 + mi*16 + lr;
            float2 c0 = make_float2(acc[mi][nj][0], acc[mi][nj][1]);
            float2 c1 = make_float2(acc[mi][nj][2], acc[mi][nj][3]);
            *(float2*)&g_cc[(size_t)row*256 + col]     = c0;
            *(float2*)&g_cc[(size_t)(row+8)*256 + col] = c1;
            float2 h0 = *(const float2*)&g_hw[(size_t)row*256 + col];
            float2 h1 = *(const float2*)&g_hw[(size_t)(row+8)*256 + col];
            int r0rel = (row >= bsplit) ? 1 : 0;
            int r1rel = (row + 8 >= bsplit) ? 1 : 0;
            s0[r0rel] += c0.x + h0.x;  s1[r0rel] += c0.y + h0.y;
            s0[r1rel] += c1.x + h1.x;  s1[r1rel] += c1.y + h1.y;
        }
        atomicAdd(&scol[0][colr],   s0[0]);
        atomicAdd(&scol[0][colr+1], s1[0]);
        if (s0[1] != 0.f || s1[1] != 0.f) {
            atomicAdd(&scol[1][colr],   s0[1]);
            atomicAdd(&scol[1][colr+1], s1[1]);
        }
    }
    __syncthreads();
    if (tid < 128) {
        atomicAdd(&g_asum[bimg*256 + col0 + tid], scol[0][tid]);
        float v1 = scol[1][tid];
        if (v1 != 0.f && bimg + 1 < Bc)
            atomicAdd(&g_asum[(bimg+1)*256 + col0 + tid], v1);
    }
}

// ---------- tiny reweight MLP + pairwise softmax ----------
__global__ __launch_bounds__(256) void k_small(const float* __restrict__ fc1w,
                                               const float* __restrict__ fc1b,
                                               const float* __restrict__ fc2w,
                                               const float* __restrict__ fc2b) {
    __shared__ float sm[16][256];
    __shared__ float sh1[16][64];
    int tid = threadIdx.x;
    const float inv = 1.0f / (float)HWp;
    for (int i = tid; i < 16*256; i += 256) sm[i >> 8][i & 255] = g_asum[i] * inv;
    __syncthreads();
    for (int idx = tid; idx < 16*64; idx += 256) {
        int b = idx >> 6, o = idx & 63;
        float a = fc1b[o];
        #pragma unroll 4
        for (int c = 0; c < 256; c++) a += sm[b][c] * fc1w[(size_t)o*256 + c];
        a = 0.5f * a * (1.0f + erff(a * 0.70710678118654752f));
        sh1[b][o] = a;
    }
    __syncthreads();
    for (int idx = tid; idx < 16*256; idx += 256) {
        int b = idx >> 8, c = idx & 255;
        float l0 = fc2b[2*c], l1 = fc2b[2*c+1];
        #pragma unroll 4
        for (int k = 0; k < 64; k++) {
            float hv = sh1[b][k];
            l0 += hv * fc2w[(size_t)(2*c)*64 + k];
            l1 += hv * fc2w[(size_t)(2*c+1)*64 + k];
        }
        float m = fmaxf(l0, l1);
        float e0 = expf(l0 - m), e1 = expf(l1 - m);
        float s = 1.f / (e0 + e1);
        g_a0[idx] = e0 * s;
        g_a1[idx] = e1 * s;
    }
}

// ---------- final GEMM: out = (hw*a0 + c*a1) @ projcnn_w^T + b  (double-buffered) ----------
__global__ __launch_bounds__(256) void k_mma_out(const float* __restrict__ wp,
                                                 const float* __restrict__ bp,
                                                 float* __restrict__ out) {
    extern __shared__ float dsm[];
    __shared__ float sa0[512], sa1[512];
    int tid = threadIdx.x, wid = tid >> 5, lane = tid & 31;
    int lr = lane >> 2, lc = lane & 3;
    int wm = wid & 3, wn = wid >> 2;
    int row0 = blockIdx.x * 128, col0 = blockIdx.y * 128;
    int bimg = row0 / HWp;
    int bimg2 = (bimg + 1 < Bc) ? bimg + 1 : bimg;
    int bsplit = (bimg + 1) * HWp;
    sa0[tid]       = g_a0[bimg*256 + tid];
    sa1[tid]       = g_a1[bimg*256 + tid];
    sa0[256 + tid] = g_a0[bimg2*256 + tid];
    sa1[256 + tid] = g_a1[bimg2*256 + tid];

    float acc[2][8][4] = {};
    float4 fh[4], fc4[4], fb[4];
    #pragma unroll
    for (int t = 0; t < 4; t++) { int idx = tid + t*256, r = idx >> 3, j = idx & 7;
        size_t p = (size_t)(row0 + r)*256 + j*4;
        fh[t]  = *(const float4*)&g_hw[p];
        fc4[t] = *(const float4*)&g_cc[p];
        fb[t]  = *(const float4*)&wp[(size_t)(col0 + r)*256 + j*4]; }
    __syncthreads();   // sa ready
    #pragma unroll
    for (int t = 0; t < 4; t++) {
        int idx = tid + t*256, r = idx >> 3, j = idx & 7;
        int rel = ((row0 + r) >= bsplit) ? 256 : 0;
        int ki = rel + j*4;
        float4 v;
        v.x = fh[t].x * sa0[ki+0] + fc4[t].x * sa1[ki+0];
        v.y = fh[t].y * sa0[ki+1] + fc4[t].y * sa1[ki+1];
        v.z = fh[t].z * sa0[ki+2] + fc4[t].z * sa1[ki+2];
        v.w = fh[t].w * sa0[ki+3] + fc4[t].w * sa1[ki+3];
        *(float4*)&dsm[r*SA + j*4]        = tf4(v);
        *(float4*)&dsm[4608 + r*SA + j*4] = tf4(fb[t]);
    }
    __syncthreads();

    for (int ch = 0; ch < 8; ch++) {
        int p = ch & 1, q = p ^ 1;
        int k0 = (ch + 1) * 32;
        if (ch < 7) {
            #pragma unroll
            for (int t = 0; t < 4; t++) { int idx = tid + t*256, r = idx >> 3, j = idx & 7;
                size_t pp = (size_t)(row0 + r)*256 + k0 + j*4;
                fh[t]  = *(const float4*)&g_hw[pp];
                fc4[t] = *(const float4*)&g_cc[pp];
                fb[t]  = *(const float4*)&wp[(size_t)(col0 + r)*256 + k0 + j*4]; }
        }
        const float* Ab = &dsm[p*BUF];
        const float* Bb = &dsm[p*BUF + 4608];
        #pragma unroll
        for (int s = 0; s < 4; s++) {
            uint32_t a[2][4];
            #pragma unroll
            for (int mi = 0; mi < 2; mi++) {
                const float* Ap = &Ab[(wm*32 + mi*16 + lr)*SA + s*8 + lc];
                a[mi][0] = __float_as_uint(Ap[0]);
                a[mi][1] = __float_as_uint(Ap[8*SA]);
                a[mi][2] = __float_as_uint(Ap[4]);
                a[mi][3] = __float_as_uint(Ap[8*SA + 4]);
            }
            #pragma unroll
            for (int nj = 0; nj < 8; nj++) {
                const float* Bp = &Bb[(wn*64 + nj*8 + lr)*SA + s*8 + lc];
                uint32_t b0 = __float_as_uint(Bp[0]);
                uint32_t b1 = __float_as_uint(Bp[4]);
                mma_t(acc[0][nj], a[0], b0, b1);
                mma_t(acc[1][nj], a[1], b0, b1);
            }
        }
        if (ch < 7) {
            #pragma unroll
            for (int t = 0; t < 4; t++) {
                int idx = tid + t*256, r = idx >> 3, j = idx & 7;
                int rel = ((row0 + r) >= bsplit) ? 256 : 0;
                int ki = rel + k0 + j*4;
                float4 v;
                v.x = fh[t].x * sa0[ki+0] + fc4[t].x * sa1[ki+0];
                v.y = fh[t].y * sa0[ki+1] + fc4[t].y * sa1[ki+1];
                v.z = fh[t].z * sa0[ki+2] + fc4[t].z * sa1[ki+2];
                v.w = fh[t].w * sa0[ki+3] + fc4[t].w * sa1[ki+3];
                *(float4*)&dsm[q*BUF + r*SA + j*4]        = tf4(v);
                *(float4*)&dsm[q*BUF + 4608 + r*SA + j*4] = tf4(fb[t]);
            }
        }
        __syncthreads();
    }

    #pragma unroll
    for (int mi = 0; mi < 2; mi++) {
        int row = row0 + wm*32 + mi*16 + lr;
        #pragma unroll
        for (int nj = 0; nj < 8; nj++) {
            int col = col0 + wn*64 + nj*8 + lc*2;
            float bb0 = __ldg(&bp[col]), bb1 = __ldg(&bp[col+1]);
            *(float2*)&out[(size_t)row*256 + col] =
                make_float2(acc[mi][nj][0] + bb0, acc[mi][nj][1] + bb1);
            *(float2*)&out[(size_t)(row+8)*256 + col] =
                make_float2(acc[mi][nj][2] + bb0, acc[mi][nj][3] + bb1);
        }
    }
}

extern "C" void kernel_launch(void* const* d_in, const int* in_sizes, int n_in,
                              void* d_out, int out_size) {
    const float* x        = (const float*)d_in[0];
    const float* conv1_w  = (const float*)d_in[1];
    const float* conv1_b  = (const float*)d_in[2];
    const float* bn_gamma = (const float*)d_in[3];
    const float* bn_beta  = (const float*)d_in[4];
    const float* conv2_w  = (const float*)d_in[5];
    const float* conv2_b  = (const float*)d_in[6];
    const float* mlp_c_w  = (const float*)d_in[7];
    const float* fc1_w    = (const float*)d_in[8];
    const float* fc1_b    = (const float*)d_in[9];
    const float* fc2_w    = (const float*)d_in[10];
    const float* fc2_b    = (const float*)d_in[11];
    const float* projcnn_w= (const float*)d_in[12];
    const float* projcnn_b= (const float*)d_in[13];
    float* out = (float*)d_out;

    const int DSM = 2 * BUF * 4;   // 73728 bytes
    cudaFuncSetAttribute(k_mma_c,   cudaFuncAttributeMaxDynamicSharedMemorySize, DSM);
    cudaFuncSetAttribute(k_mma_out, cudaFuncAttributeMaxDynamicSharedMemorySize, DSM);

    k_zero  <<<1, 256>>>();
    k_mma_g1<<<Nn/128, 256>>>(x, conv1_w, conv1_b);
    k_mma_kg<<<Nn/128, 256>>>(bn_gamma, bn_beta, conv2_w, conv2_b);
    k_invo2 <<<dim3(Bc*Hh, 8), 256>>>(x);
    dim3 g2(Nn/128, Cch/128);
    k_mma_c <<<g2, 256, DSM>>>(x, mlp_c_w);
    k_small <<<1, 256>>>(fc1_w, fc1_b, fc2_w, fc2_b);
    k_mma_out<<<g2, 256, DSM>>>(projcnn_w, projcnn_b, out);
}

// round 5
// speedup vs baseline: 3.0525x; 1.9144x over previous
#include <cuda_runtime.h>
#include <math.h>
#include <stdint.h>

#define Bc   16
#define Hh   56
#define Wd   56
#define Cch  256
#define C4c  64
#define GKK  72
#define HWp  (Hh*Wd)      // 3136
#define Nn   (Bc*HWp)     // 50176
#define EPSv 1e-5f

// ---- scratch (device globals) ----
__device__ float g_t[(size_t)Nn*C4c];
__device__ float g_wk[(size_t)Nn*GKK];
__device__ float g_hw[(size_t)Nn*Cch];
__device__ float g_cc[(size_t)Nn*Cch];
__device__ float g_xr[(size_t)Nn*Cch];    // x rounded+permuted
__device__ float g_y [(size_t)Nn*Cch];    // (hw*a0+cc*a1) rounded+permuted
__device__ float g_wmr[Cch*Cch];          // mlp_c_w rounded+permuted
__device__ float g_wpr[Cch*Cch];          // projcnn_w rounded+permuted
__device__ float g_sum[C4c];
__device__ float g_sumsq[C4c];
__device__ float g_asum[Bc*Cch];
__device__ float g_a0[Bc*Cch];
__device__ float g_a1[Bc*Cch];

// ================= helpers =================
__device__ __forceinline__ uint32_t f2tf(float f) {
    uint32_t r;
    asm("cvt.rna.tf32.f32 %0, %1;" : "=r"(r) : "f"(f));
    return r;
}
__device__ __forceinline__ float rtf(float f) { return __uint_as_float(f2tf(f)); }
__device__ __forceinline__ float4 tf4(float4 v) {
    v.x = rtf(v.x); v.y = rtf(v.y); v.z = rtf(v.z); v.w = rtf(v.w);
    return v;
}
__device__ __forceinline__ void mma_t(float* c, const uint32_t* a, uint32_t b0, uint32_t b1) {
    asm volatile(
        "mma.sync.aligned.m16n8k8.row.col.f32.tf32.tf32.f32 "
        "{%0,%1,%2,%3}, {%4,%5,%6,%7}, {%8,%9}, {%0,%1,%2,%3};"
        : "+f"(c[0]), "+f"(c[1]), "+f"(c[2]), "+f"(c[3])
        : "r"(a[0]), "r"(a[1]), "r"(a[2]), "r"(a[3]), "r"(b0), "r"(b1));
}
__device__ __forceinline__ uint32_t smem_u32(const void* p) {
    uint32_t a;
    asm("{ .reg .u64 t; cvta.to.shared.u64 t, %1; cvt.u32.u64 %0, t; }" : "=r"(a) : "l"(p));
    return a;
}
__device__ __forceinline__ void cp16(uint32_t dst, const void* src) {
    asm volatile("cp.async.cg.shared.global [%0], [%1], 16;" :: "r"(dst), "l"(src));
}
#define CP_COMMIT() asm volatile("cp.async.commit_group;")
#define CP_WAIT1()  asm volatile("cp.async.wait_group 1;")
#define CP_WAIT0()  asm volatile("cp.async.wait_group 0;")

#define SA 36          // legacy stride for g1/kg kernels
#define ST 48          // permuted-layout row stride (floats), conflict-free LDS.128
#define STGF (256*ST)  // floats per pipeline stage (A 128 rows + B 128 rows)
#define DSMC (2*STGF*4)

// ============================ kernels ============================

__global__ void k_zero() {
    int tid = threadIdx.x;
    if (tid < C4c) { g_sum[tid] = 0.f; g_sumsq[tid] = 0.f; }
    for (int i = tid; i < Bc*Cch; i += 256) g_asum[i] = 0.f;
}

// ---------- round + permute x into g_xr (k-within-16 transpose) ----------
__global__ __launch_bounds__(256) void k_round_x(const float* __restrict__ x) {
    size_t idx = (size_t)blockIdx.x * 256 + threadIdx.x;   // one k16 group
    size_t base = idx * 16;
    float4 v0 = *(const float4*)&x[base];
    float4 v1 = *(const float4*)&x[base + 4];
    float4 v2 = *(const float4*)&x[base + 8];
    float4 v3 = *(const float4*)&x[base + 12];
    float4 o0 = tf4(make_float4(v0.x, v1.x, v2.x, v3.x));
    float4 o1 = tf4(make_float4(v0.y, v1.y, v2.y, v3.y));
    float4 o2 = tf4(make_float4(v0.z, v1.z, v2.z, v3.z));
    float4 o3 = tf4(make_float4(v0.w, v1.w, v2.w, v3.w));
    *(float4*)&g_xr[base]      = o0;
    *(float4*)&g_xr[base + 4]  = o1;
    *(float4*)&g_xr[base + 8]  = o2;
    *(float4*)&g_xr[base + 12] = o3;
}

// ---------- round + permute mlp_c_w / projcnn_w ----------
__global__ __launch_bounds__(256) void k_round_w(const float* __restrict__ wm,
                                                 const float* __restrict__ wp) {
    int idx = blockIdx.x * 256 + threadIdx.x;       // 8192 groups total
    const float* src = (idx < 4096) ? wm : wp;
    float*       dst = (idx < 4096) ? g_wmr : g_wpr;
    size_t base = (size_t)(idx & 4095) * 16;
    float4 v0 = *(const float4*)&src[base];
    float4 v1 = *(const float4*)&src[base + 4];
    float4 v2 = *(const float4*)&src[base + 8];
    float4 v3 = *(const float4*)&src[base + 12];
    *(float4*)&dst[base]      = tf4(make_float4(v0.x, v1.x, v2.x, v3.x));
    *(float4*)&dst[base + 4]  = tf4(make_float4(v0.y, v1.y, v2.y, v3.y));
    *(float4*)&dst[base + 8]  = tf4(make_float4(v0.z, v1.z, v2.z, v3.z));
    *(float4*)&dst[base + 12] = tf4(make_float4(v0.w, v1.w, v2.w, v3.w));
}

// ---------- GEMM1: t = x @ conv1_w^T + b ; fused BN stats (unchanged, known-good) ----------
__global__ __launch_bounds__(256) void k_mma_g1(const float* __restrict__ x,
                                                const float* __restrict__ w1,
                                                const float* __restrict__ b1) {
    __shared__ float As[128*SA];
    __shared__ float Bs[64*SA];
    __shared__ float scol[64], ssq[64];
    int tid = threadIdx.x, wid = tid >> 5, lane = tid & 31;
    int lr = lane >> 2, lc = lane & 3;
    int wm = wid & 3, wn = wid >> 2;
    int row0 = blockIdx.x * 128;
    if (tid < 64) { scol[tid] = 0.f; ssq[tid] = 0.f; }

    float acc[2][4][4] = {};
    float4 fa[4], fb[2];
    #pragma unroll
    for (int t = 0; t < 4; t++) { int idx = tid + t*256, r = idx >> 3, j = idx & 7;
        fa[t] = *(const float4*)&x[(size_t)(row0 + r)*256 + j*4]; }
    #pragma unroll
    for (int t = 0; t < 2; t++) { int idx = tid + t*256, r = idx >> 3, j = idx & 7;
        fb[t] = *(const float4*)&w1[(size_t)r*256 + j*4]; }

    for (int ch = 0; ch < 8; ch++) {
        if (ch) __syncthreads();
        #pragma unroll
        for (int t = 0; t < 4; t++) { int idx = tid + t*256, r = idx >> 3, j = idx & 7;
            *(float4*)&As[r*SA + j*4] = tf4(fa[t]); }
        #pragma unroll
        for (int t = 0; t < 2; t++) { int idx = tid + t*256, r = idx >> 3, j = idx & 7;
            *(float4*)&Bs[r*SA + j*4] = tf4(fb[t]); }
        __syncthreads();
        if (ch < 7) {
            int k0 = (ch + 1) * 32;
            #pragma unroll
            for (int t = 0; t < 4; t++) { int idx = tid + t*256, r = idx >> 3, j = idx & 7;
                fa[t] = *(const float4*)&x[(size_t)(row0 + r)*256 + k0 + j*4]; }
            #pragma unroll
            for (int t = 0; t < 2; t++) { int idx = tid + t*256, r = idx >> 3, j = idx & 7;
                fb[t] = *(const float4*)&w1[(size_t)r*256 + k0 + j*4]; }
        }
        #pragma unroll
        for (int s = 0; s < 4; s++) {
            uint32_t a[2][4];
            #pragma unroll
            for (int mi = 0; mi < 2; mi++) {
                const float* Ap = &As[(wm*32 + mi*16 + lr)*SA + s*8 + lc];
                a[mi][0] = __float_as_uint(Ap[0]);
                a[mi][1] = __float_as_uint(Ap[8*SA]);
                a[mi][2] = __float_as_uint(Ap[4]);
                a[mi][3] = __float_as_uint(Ap[8*SA + 4]);
            }
            #pragma unroll
            for (int nj = 0; nj < 4; nj++) {
                const float* Bp = &Bs[(wn*32 + nj*8 + lr)*SA + s*8 + lc];
                uint32_t b0 = __float_as_uint(Bp[0]);
                uint32_t b1 = __float_as_uint(Bp[4]);
                mma_t(acc[0][nj], a[0], b0, b1);
                mma_t(acc[1][nj], a[1], b0, b1);
            }
        }
    }
    __syncthreads();

    #pragma unroll
    for (int nj = 0; nj < 4; nj++) {
        int c0 = wn*32 + nj*8 + lc*2;
        float bb0 = __ldg(&b1[c0]), bb1 = __ldg(&b1[c0+1]);
        float s0 = 0.f, s1 = 0.f, q0 = 0.f, q1 = 0.f;
        #pragma unroll
        for (int mi = 0; mi < 2; mi++) {
            int row = row0 + wm*32 + mi*16 + lr;
            float v0 = acc[mi][nj][0] + bb0;
            float v1 = acc[mi][nj][1] + bb1;
            float v2 = acc[mi][nj][2] + bb0;
            float v3 = acc[mi][nj][3] + bb1;
            *(float2*)&g_t[(size_t)row*64 + c0]     = make_float2(v0, v1);
            *(float2*)&g_t[(size_t)(row+8)*64 + c0] = make_float2(v2, v3);
            s0 += v0 + v2; s1 += v1 + v3;
            q0 += v0*v0 + v2*v2; q1 += v1*v1 + v3*v3;
        }
        atomicAdd(&scol[c0], s0);   atomicAdd(&scol[c0+1], s1);
        atomicAdd(&ssq[c0],  q0);   atomicAdd(&ssq[c0+1],  q1);
    }
    __syncthreads();
    if (tid < 64) {
        atomicAdd(&g_sum[tid],   scol[tid]);
        atomicAdd(&g_sumsq[tid], ssq[tid]);
    }
}

// ---------- kernel-gen (tf32 MMA, unchanged) ----------
__global__ __launch_bounds__(256) void k_mma_kg(const float* __restrict__ gamma,
                                                const float* __restrict__ beta,
                                                const float* __restrict__ w2,
                                                const float* __restrict__ b2) {
    __shared__ float As[128*SA];
    __shared__ float Bs[80*SA];
    __shared__ float sc[64], shf[64];
    int tid = threadIdx.x, wid = tid >> 5, lane = tid & 31;
    int lr = lane >> 2, lc = lane & 3;
    int wm = wid & 3, wn = wid >> 2;
    int row0 = blockIdx.x * 128;
    if (tid < 64) {
        const float invN = 1.0f / (float)Nn;
        float mu  = g_sum[tid] * invN;
        float var = g_sumsq[tid] * invN - mu * mu;
        float s = gamma[tid] * rsqrtf(var + EPSv);
        sc[tid]  = s;
        shf[tid] = beta[tid] - mu * s;
    }
    __syncthreads();

    float acc[2][5][4] = {};
    for (int ch = 0; ch < 2; ch++) {
        if (ch) __syncthreads();
        #pragma unroll
        for (int t = 0; t < 4; t++) {
            int idx = tid + t*256, r = idx >> 3, j = idx & 7;
            int c = ch*32 + j*4;
            float4 v = *(const float4*)&g_t[(size_t)(row0 + r)*64 + c];
            v.x = fmaxf(fmaf(v.x, sc[c+0], shf[c+0]), 0.f);
            v.y = fmaxf(fmaf(v.y, sc[c+1], shf[c+1]), 0.f);
            v.z = fmaxf(fmaf(v.z, sc[c+2], shf[c+2]), 0.f);
            v.w = fmaxf(fmaf(v.w, sc[c+3], shf[c+3]), 0.f);
            *(float4*)&As[r*SA + j*4] = tf4(v);
        }
        for (int idx = tid; idx < 80*8; idx += 256) {
            int r = idx >> 3, j = idx & 7;
            float4 v = make_float4(0.f, 0.f, 0.f, 0.f);
            if (r < 72) v = *(const float4*)&w2[(size_t)r*64 + ch*32 + j*4];
            *(float4*)&Bs[r*SA + j*4] = tf4(v);
        }
        __syncthreads();
        #pragma unroll
        for (int s = 0; s < 4; s++) {
            uint32_t a[2][4];
            #pragma unroll
            for (int mi = 0; mi < 2; mi++) {
                const float* Ap = &As[(wm*32 + mi*16 + lr)*SA + s*8 + lc];
                a[mi][0] = __float_as_uint(Ap[0]);
                a[mi][1] = __float_as_uint(Ap[8*SA]);
                a[mi][2] = __float_as_uint(Ap[4]);
                a[mi][3] = __float_as_uint(Ap[8*SA + 4]);
            }
            #pragma unroll
            for (int nj = 0; nj < 5; nj++) {
                const float* Bp = &Bs[(wn*40 + nj*8 + lr)*SA + s*8 + lc];
                uint32_t b0 = __float_as_uint(Bp[0]);
                uint32_t b1 = __float_as_uint(Bp[4]);
                mma_t(acc[0][nj], a[0], b0, b1);
                mma_t(acc[1][nj], a[1], b0, b1);
            }
        }
    }

    #pragma unroll
    for (int mi = 0; mi < 2; mi++) {
        int row = row0 + wm*32 + mi*16 + lr;
        #pragma unroll
        for (int nj = 0; nj < 5; nj++) {
            int col = wn*40 + nj*8 + lc*2;
            if (col < 72) {
                float bb0 = __ldg(&b2[col]), bb1 = __ldg(&b2[col+1]);
                *(float2*)&g_wk[(size_t)row*72 + col] =
                    make_float2(acc[mi][nj][0] + bb0, acc[mi][nj][1] + bb1);
                *(float2*)&g_wk[(size_t)(row+8)*72 + col] =
                    make_float2(acc[mi][nj][2] + bb0, acc[mi][nj][3] + bb1);
            }
        }
    }
}

// ---------- involution (row-tiled, unchanged) ----------
__global__ __launch_bounds__(256) void k_invo2(const float* __restrict__ x) {
    __shared__ float xs[3][58][32];
    __shared__ float ws[56][9];
    int bh = blockIdx.x;
    int g  = blockIdx.y;
    int b = bh / Hh, h = bh % Hh;
    int tid = threadIdx.x;

    if (tid < 192) {
        int dy = tid / 64, e = (tid >> 5) & 1, c = tid & 31;
        xs[dy][e ? 57 : 0][c] = 0.f;
    }
    for (int i = tid; i < 3*56*8; i += 256) {
        int c4 = i & 7, w = (i >> 3) % 56, dy = i / 448;
        int hh = h + dy - 1;
        float4 v = make_float4(0.f, 0.f, 0.f, 0.f);
        if (hh >= 0 && hh < Hh)
            v = *(const float4*)&x[(((size_t)(b*Hh + hh))*Wd + w)*256 + g*32 + c4*4];
        *(float4*)&xs[dy][1 + w][c4*4] = v;
    }
    for (int i = tid; i < 56*9; i += 256) {
        int w = i / 9, k = i % 9;
        ws[w][k] = g_wk[((size_t)bh*Wd + w)*72 + g*9 + k];
    }
    __syncthreads();

    int c = tid & 31, wq = tid >> 5;
    #pragma unroll
    for (int i = 0; i < 7; i++) {
        int w = wq + i*8;
        float acc = 0.f;
        #pragma unroll
        for (int dy = 0; dy < 3; dy++)
            #pragma unroll
            for (int dx = 0; dx < 3; dx++)
                acc += ws[w][dy*3 + dx] * xs[dy][w + dx][c];
        g_hw[(((size_t)bh)*Wd + w)*256 + g*32 + c] = acc;
    }
}

// ================= cp.async 64x64-warp-tile GEMM core =================
// A rows at dsm[stage], B rows at dsm[stage]+128*ST, k permuted per 16-group.
__device__ __forceinline__ void gemm_core(const float* __restrict__ Ag,
                                          const float* __restrict__ Bg,
                                          int row0, int col0,
                                          float acc[4][8][4],
                                          float* dsm, uint32_t sbase,
                                          int tid, int wm, int wn, int lr, int lc) {
    auto stage_cp = [&](int ch, int s) {
        uint32_t sb0 = sbase + (uint32_t)(s * STGF * 4);
        int k0 = ch * 32;
        #pragma unroll
        for (int i = 0; i < 8; i++) {
            int idx = tid + i*128, r = idx >> 3, q = idx & 7;
            cp16(sb0 + (uint32_t)((r*ST + q*4)*4),
                 &Ag[(size_t)(row0 + r)*256 + k0 + q*4]);
        }
        #pragma unroll
        for (int i = 0; i < 8; i++) {
            int idx = tid + i*128, r = idx >> 3, q = idx & 7;
            cp16(sb0 + (uint32_t)((128*ST + r*ST + q*4)*4),
                 &Bg[(size_t)(col0 + r)*256 + k0 + q*4]);
        }
        CP_COMMIT();
    };
    stage_cp(0, 0);
    stage_cp(1, 1);

    for (int ch = 0; ch < 8; ch++) {
        if (ch < 7) CP_WAIT1(); else CP_WAIT0();
        __syncthreads();
        const float* Ab = dsm + (ch & 1) * STGF;
        const float* Bb = Ab + 128*ST;
        #pragma unroll
        for (int g = 0; g < 2; g++) {
            float4 Alo[4], Ahi[4], Bv[8];
            #pragma unroll
            for (int mi = 0; mi < 4; mi++) {
                Alo[mi] = *(const float4*)&Ab[(wm*64 + mi*16 + lr)*ST + g*16 + lc*4];
                Ahi[mi] = *(const float4*)&Ab[(wm*64 + mi*16 + 8 + lr)*ST + g*16 + lc*4];
            }
            #pragma unroll
            for (int nj = 0; nj < 8; nj++)
                Bv[nj] = *(const float4*)&Bb[(wn*64 + nj*8 + lr)*ST + g*16 + lc*4];
            #pragma unroll
            for (int mi = 0; mi < 4; mi++) {
                uint32_t a0[4] = { __float_as_uint(Alo[mi].x), __float_as_uint(Ahi[mi].x),
                                   __float_as_uint(Alo[mi].y), __float_as_uint(Ahi[mi].y) };
                uint32_t a1[4] = { __float_as_uint(Alo[mi].z), __float_as_uint(Ahi[mi].z),
                                   __float_as_uint(Alo[mi].w), __float_as_uint(Ahi[mi].w) };
                #pragma unroll
                for (int nj = 0; nj < 8; nj++) {
                    mma_t(acc[mi][nj], a0, __float_as_uint(Bv[nj].x), __float_as_uint(Bv[nj].y));
                    mma_t(acc[mi][nj], a1, __float_as_uint(Bv[nj].z), __float_as_uint(Bv[nj].w));
                }
            }
        }
        __syncthreads();
        if (ch < 6) stage_cp(ch + 2, ch & 1);
    }
}

// ---------- GEMM c = xr @ wmr^T  + fused (hw+c) spatial-mean ----------
__global__ __launch_bounds__(128) void k_mma_c2() {
    extern __shared__ float dsm[];
    __shared__ float scol[2][128];
    int tid = threadIdx.x, wid = tid >> 5, lane = tid & 31;
    int lr = lane >> 2, lc = lane & 3;
    int wm = wid >> 1, wn = wid & 1;
    int row0 = blockIdx.x * 128, col0 = blockIdx.y * 128;
    scol[0][tid] = 0.f; scol[1][tid] = 0.f;
    uint32_t sbase = smem_u32(dsm);

    float acc[4][8][4] = {};
    gemm_core(g_xr, g_wmr, row0, col0, acc, dsm, sbase, tid, wm, wn, lr, lc);

    int bimg = row0 / HWp;
    int bsplit = (bimg + 1) * HWp;
    #pragma unroll
    for (int nj = 0; nj < 8; nj++) {
        int colr = wn*64 + nj*8 + lc*2;
        int col = col0 + colr;
        float s0[2] = {0.f, 0.f}, s1[2] = {0.f, 0.f};
        #pragma unroll
        for (int mi = 0; mi < 4; mi++) {
            int row = row0 + wm*64 + mi*16 + lr;
            float2 c0 = make_float2(acc[mi][nj][0], acc[mi][nj][1]);
            float2 c1 = make_float2(acc[mi][nj][2], acc[mi][nj][3]);
            *(float2*)&g_cc[(size_t)row*256 + col]     = c0;
            *(float2*)&g_cc[(size_t)(row+8)*256 + col] = c1;
            float2 h0 = *(const float2*)&g_hw[(size_t)row*256 + col];
            float2 h1 = *(const float2*)&g_hw[(size_t)(row+8)*256 + col];
            int r0 = (row >= bsplit) ? 1 : 0;
            int r1 = (row + 8 >= bsplit) ? 1 : 0;
            s0[r0] += c0.x + h0.x;  s1[r0] += c0.y + h0.y;
            s0[r1] += c1.x + h1.x;  s1[r1] += c1.y + h1.y;
        }
        atomicAdd(&scol[0][colr],   s0[0]);
        atomicAdd(&scol[0][colr+1], s1[0]);
        if (s0[1] != 0.f || s1[1] != 0.f) {
            atomicAdd(&scol[1][colr],   s0[1]);
            atomicAdd(&scol[1][colr+1], s1[1]);
        }
    }
    __syncthreads();
    atomicAdd(&g_asum[bimg*256 + col0 + tid], scol[0][tid]);
    float v1 = scol[1][tid];
    if (v1 != 0.f && bimg + 1 < Bc)
        atomicAdd(&g_asum[(bimg+1)*256 + col0 + tid], v1);
}

// ---------- reweight MLP + pairwise softmax: one block per image ----------
__global__ __launch_bounds__(256) void k_small2(const float* __restrict__ fc1w,
                                                const float* __restrict__ fc1b,
                                                const float* __restrict__ fc2w,
                                                const float* __restrict__ fc2b) {
    __shared__ float sm[256];
    __shared__ float h1[64];
    int b = blockIdx.x, tid = threadIdx.x;
    sm[tid] = g_asum[b*256 + tid] * (1.0f / (float)HWp);
    __syncthreads();
    int o = tid >> 2, qtr = tid & 3;
    {
        const float* w = &fc1w[(size_t)o*256 + qtr*64];
        const float* s = &sm[qtr*64];
        float p = 0.f;
        #pragma unroll 8
        for (int c = 0; c < 64; c++) p += s[c] * w[c];
        p += __shfl_xor_sync(0xffffffffu, p, 1);
        p += __shfl_xor_sync(0xffffffffu, p, 2);
        if (qtr == 0) {
            float a = p + fc1b[o];
            h1[o] = 0.5f * a * (1.0f + erff(a * 0.70710678118654752f));
        }
    }
    __syncthreads();
    int c = tid;
    float l0 = fc2b[2*c], l1 = fc2b[2*c+1];
    #pragma unroll 8
    for (int k = 0; k < 64; k++) {
        float hv = h1[k];
        l0 += hv * fc2w[(size_t)(2*c)*64 + k];
        l1 += hv * fc2w[(size_t)(2*c+1)*64 + k];
    }
    float m = fmaxf(l0, l1);
    float e0 = expf(l0 - m), e1 = expf(l1 - m);
    float s = 1.f / (e0 + e1);
    g_a0[b*256 + c] = e0 * s;
    g_a1[b*256 + c] = e1 * s;
}

// ---------- y = rna(hw*a0 + cc*a1), permuted ----------
__global__ __launch_bounds__(256) void k_prey() {
    size_t idx = (size_t)blockIdx.x * 256 + threadIdx.x;
    int row = (int)(idx >> 4), g = (int)(idx & 15);
    size_t base = (size_t)row * 256 + g * 16;
    int bimg = row / HWp;
    const float* pa0 = &g_a0[bimg*256 + g*16];
    const float* pa1 = &g_a1[bimg*256 + g*16];
    float v[16];
    #pragma unroll
    for (int j = 0; j < 4; j++) {
        float4 hv = *(const float4*)&g_hw[base + j*4];
        float4 cv = *(const float4*)&g_cc[base + j*4];
        float4 a0 = *(const float4*)&pa0[j*4];
        float4 a1 = *(const float4*)&pa1[j*4];
        v[j*4+0] = hv.x*a0.x + cv.x*a1.x;
        v[j*4+1] = hv.y*a0.y + cv.y*a1.y;
        v[j*4+2] = hv.z*a0.z + cv.z*a1.z;
        v[j*4+3] = hv.w*a0.w + cv.w*a1.w;
    }
    #pragma unroll
    for (int j = 0; j < 4; j++)
        *(float4*)&g_y[base + j*4] = tf4(make_float4(v[j], v[4+j], v[8+j], v[12+j]));
}

// ---------- final GEMM: out = y @ wpr^T + bias ----------
__global__ __launch_bounds__(128) void k_mma_out2(const float* __restrict__ bp,
                                                  float* __restrict__ out) {
    extern __shared__ float dsm[];
    int tid = threadIdx.x, wid = tid >> 5, lane = tid & 31;
    int lr = lane >> 2, lc = lane & 3;
    int wm = wid >> 1, wn = wid & 1;
    int row0 = blockIdx.x * 128, col0 = blockIdx.y * 128;
    uint32_t sbase = smem_u32(dsm);

    float acc[4][8][4] = {};
    gemm_core(g_y, g_wpr, row0, col0, acc, dsm, sbase, tid, wm, wn, lr, lc);

    #pragma unroll
    for (int nj = 0; nj < 8; nj++) {
        int col = col0 + wn*64 + nj*8 + lc*2;
        float bb0 = __ldg(&bp[col]), bb1 = __ldg(&bp[col+1]);
        #pragma unroll
        for (int mi = 0; mi < 4; mi++) {
            int row = row0 + wm*64 + mi*16 + lr;
            *(float2*)&out[(size_t)row*256 + col] =
                make_float2(acc[mi][nj][0] + bb0, acc[mi][nj][1] + bb1);
            *(float2*)&out[(size_t)(row+8)*256 + col] =
                make_float2(acc[mi][nj][2] + bb0, acc[mi][nj][3] + bb1);
        }
    }
}

extern "C" void kernel_launch(void* const* d_in, const int* in_sizes, int n_in,
                              void* d_out, int out_size) {
    const float* x        = (const float*)d_in[0];
    const float* conv1_w  = (const float*)d_in[1];
    const float* conv1_b  = (const float*)d_in[2];
    const float* bn_gamma = (const float*)d_in[3];
    const float* bn_beta  = (const float*)d_in[4];
    const float* conv2_w  = (const float*)d_in[5];
    const float* conv2_b  = (const float*)d_in[6];
    const float* mlp_c_w  = (const float*)d_in[7];
    const float* fc1_w    = (const float*)d_in[8];
    const float* fc1_b    = (const float*)d_in[9];
    const float* fc2_w    = (const float*)d_in[10];
    const float* fc2_b    = (const float*)d_in[11];
    const float* projcnn_w= (const float*)d_in[12];
    const float* projcnn_b= (const float*)d_in[13];
    float* out = (float*)d_out;

    cudaFuncSetAttribute(k_mma_c2,   cudaFuncAttributeMaxDynamicSharedMemorySize, DSMC);
    cudaFuncSetAttribute(k_mma_out2, cudaFuncAttributeMaxDynamicSharedMemorySize, DSMC);

    k_zero   <<<1, 256>>>();
    k_round_x<<<Nn*16/256, 256>>>(x);
    k_round_w<<<32, 256>>>(mlp_c_w, projcnn_w);
    k_mma_g1 <<<Nn/128, 256>>>(x, conv1_w, conv1_b);
    k_mma_kg <<<Nn/128, 256>>>(bn_gamma, bn_beta, conv2_w, conv2_b);
    k_invo2  <<<dim3(Bc*Hh, 8), 256>>>(x);
    k_mma_c2 <<<dim3(Nn/128, 2), 128, DSMC>>>();
    k_small2 <<<Bc, 256>>>(fc1_w, fc1_b, fc2_w, fc2_b);
    k_prey   <<<Nn*16/256, 256>>>();
    k_mma_out2<<<dim3(Nn/128, 2), 128, DSMC>>>(projcnn_b, out);
}

// round 6
// speedup vs baseline: 3.1429x; 1.0296x over previous
#include <cuda_runtime.h>
#include <math.h>
#include <stdint.h>

#define Bc   16
#define Hh   56
#define Wd   56
#define Cch  256
#define C4c  64
#define GKK  72
#define HWp  (Hh*Wd)      // 3136
#define Nn   (Bc*HWp)     // 50176
#define EPSv 1e-5f

// ---- scratch (device globals) ----
__device__ float g_t[(size_t)Nn*C4c];
__device__ float g_wk[(size_t)Nn*GKK];
__device__ float g_hw[(size_t)Nn*Cch];
__device__ float g_cc[(size_t)Nn*Cch];
__device__ float g_xr[(size_t)Nn*Cch];    // x rounded+permuted
__device__ float g_y [(size_t)Nn*Cch];    // (hw*a0+cc*a1) rounded+permuted
__device__ float g_wmr[Cch*Cch];          // mlp_c_w rounded+permuted
__device__ float g_wpr[Cch*Cch];          // projcnn_w rounded+permuted
__device__ float g_w1r[C4c*Cch];          // conv1_w rounded+permuted
__device__ float g_sum[C4c];
__device__ float g_sumsq[C4c];
__device__ float g_asum[Bc*Cch];
__device__ float g_a0[Bc*Cch];
__device__ float g_a1[Bc*Cch];

// ================= helpers =================
__device__ __forceinline__ uint32_t f2tf(float f) {
    uint32_t r;
    asm("cvt.rna.tf32.f32 %0, %1;" : "=r"(r) : "f"(f));
    return r;
}
__device__ __forceinline__ float rtf(float f) { return __uint_as_float(f2tf(f)); }
__device__ __forceinline__ float4 tf4(float4 v) {
    v.x = rtf(v.x); v.y = rtf(v.y); v.z = rtf(v.z); v.w = rtf(v.w);
    return v;
}
__device__ __forceinline__ void mma_t(float* c, const uint32_t* a, uint32_t b0, uint32_t b1) {
    asm volatile(
        "mma.sync.aligned.m16n8k8.row.col.f32.tf32.tf32.f32 "
        "{%0,%1,%2,%3}, {%4,%5,%6,%7}, {%8,%9}, {%0,%1,%2,%3};"
        : "+f"(c[0]), "+f"(c[1]), "+f"(c[2]), "+f"(c[3])
        : "r"(a[0]), "r"(a[1]), "r"(a[2]), "r"(a[3]), "r"(b0), "r"(b1));
}
__device__ __forceinline__ uint32_t smem_u32(const void* p) {
    uint32_t a;
    asm("{ .reg .u64 t; cvta.to.shared.u64 t, %1; cvt.u32.u64 %0, t; }" : "=r"(a) : "l"(p));
    return a;
}
__device__ __forceinline__ void cp16(uint32_t dst, const void* src) {
    asm volatile("cp.async.cg.shared.global [%0], [%1], 16;" :: "r"(dst), "l"(src));
}
#define CP_COMMIT() asm volatile("cp.async.commit_group;")
#define CP_WAIT1()  asm volatile("cp.async.wait_group 1;")
#define CP_WAIT0()  asm volatile("cp.async.wait_group 0;")

#define SA 36          // legacy stride for kg kernel
#define ST 48          // permuted-layout row stride (floats)
#define STGF (256*ST)  // floats per stage for 128x128 core
#define DSMC (2*STGF*4)
#define STG1 (192*ST)  // floats per stage for g1 (A128 + B64)
#define DSG1 (2*STG1*4)

// ============================ kernels ============================

__global__ void k_zero() {
    int tid = threadIdx.x;
    if (tid < C4c) { g_sum[tid] = 0.f; g_sumsq[tid] = 0.f; }
    for (int i = tid; i < Bc*Cch; i += 256) g_asum[i] = 0.f;
}

// ---------- round + permute x into g_xr (k-within-16 transpose) ----------
__global__ __launch_bounds__(256) void k_round_x(const float* __restrict__ x) {
    size_t idx = (size_t)blockIdx.x * 256 + threadIdx.x;
    size_t base = idx * 16;
    float4 v0 = *(const float4*)&x[base];
    float4 v1 = *(const float4*)&x[base + 4];
    float4 v2 = *(const float4*)&x[base + 8];
    float4 v3 = *(const float4*)&x[base + 12];
    *(float4*)&g_xr[base]      = tf4(make_float4(v0.x, v1.x, v2.x, v3.x));
    *(float4*)&g_xr[base + 4]  = tf4(make_float4(v0.y, v1.y, v2.y, v3.y));
    *(float4*)&g_xr[base + 8]  = tf4(make_float4(v0.z, v1.z, v2.z, v3.z));
    *(float4*)&g_xr[base + 12] = tf4(make_float4(v0.w, v1.w, v2.w, v3.w));
}

// ---------- round + permute mlp_c_w / projcnn_w / conv1_w ----------
__global__ __launch_bounds__(256) void k_round_w(const float* __restrict__ wm,
                                                 const float* __restrict__ wp,
                                                 const float* __restrict__ w1) {
    int idx = blockIdx.x * 256 + threadIdx.x;       // 9216 groups total
    if (idx >= 9216) return;
    const float* src;  float* dst;  size_t base;
    if (idx < 4096)       { src = wm; dst = g_wmr; base = (size_t)idx * 16; }
    else if (idx < 8192)  { src = wp; dst = g_wpr; base = (size_t)(idx - 4096) * 16; }
    else                  { src = w1; dst = g_w1r; base = (size_t)(idx - 8192) * 16; }
    float4 v0 = *(const float4*)&src[base];
    float4 v1 = *(const float4*)&src[base + 4];
    float4 v2 = *(const float4*)&src[base + 8];
    float4 v3 = *(const float4*)&src[base + 12];
    *(float4*)&dst[base]      = tf4(make_float4(v0.x, v1.x, v2.x, v3.x));
    *(float4*)&dst[base + 4]  = tf4(make_float4(v0.y, v1.y, v2.y, v3.y));
    *(float4*)&dst[base + 8]  = tf4(make_float4(v0.z, v1.z, v2.z, v3.z));
    *(float4*)&dst[base + 12] = tf4(make_float4(v0.w, v1.w, v2.w, v3.w));
}

// ---------- GEMM1 (cp.async): t = xr @ w1r^T + b ; fused BN stats ----------
__global__ __launch_bounds__(128) void k_mma_g1b(const float* __restrict__ b1) {
    extern __shared__ float dsm[];
    __shared__ float scol[64], ssq[64];
    int tid = threadIdx.x, wid = tid >> 5, lane = tid & 31;
    int lr = lane >> 2, lc = lane & 3;
    int wm = wid & 1, wn = wid >> 1;    // warp tile 64 x 32
    int row0 = blockIdx.x * 128;
    if (tid < 64) { scol[tid] = 0.f; ssq[tid] = 0.f; }
    uint32_t sbase = smem_u32(dsm);

    auto stage_cp = [&](int ch, int s) {
        uint32_t sb0 = sbase + (uint32_t)(s * STG1 * 4);
        int k0 = ch * 32;
        #pragma unroll
        for (int i = 0; i < 8; i++) {
            int idx = tid + i*128, r = idx >> 3, q = idx & 7;
            cp16(sb0 + (uint32_t)((r*ST + q*4)*4),
                 &g_xr[(size_t)(row0 + r)*256 + k0 + q*4]);
        }
        #pragma unroll
        for (int i = 0; i < 4; i++) {
            int idx = tid + i*128, r = idx >> 3, q = idx & 7;
            cp16(sb0 + (uint32_t)((128*ST + r*ST + q*4)*4),
                 &g_w1r[(size_t)r*256 + k0 + q*4]);
        }
        CP_COMMIT();
    };
    stage_cp(0, 0);
    stage_cp(1, 1);

    float acc[4][4][4] = {};
    for (int ch = 0; ch < 8; ch++) {
        if (ch < 7) CP_WAIT1(); else CP_WAIT0();
        __syncthreads();
        const float* Ab = dsm + (ch & 1) * STG1;
        const float* Bb = Ab + 128*ST;
        #pragma unroll
        for (int g = 0; g < 2; g++) {
            float4 Alo[4], Ahi[4], Bv[4];
            #pragma unroll
            for (int mi = 0; mi < 4; mi++) {
                Alo[mi] = *(const float4*)&Ab[(wm*64 + mi*16 + lr)*ST + g*16 + lc*4];
                Ahi[mi] = *(const float4*)&Ab[(wm*64 + mi*16 + 8 + lr)*ST + g*16 + lc*4];
            }
            #pragma unroll
            for (int nj = 0; nj < 4; nj++)
                Bv[nj] = *(const float4*)&Bb[(wn*32 + nj*8 + lr)*ST + g*16 + lc*4];
            #pragma unroll
            for (int mi = 0; mi < 4; mi++) {
                uint32_t a0[4] = { __float_as_uint(Alo[mi].x), __float_as_uint(Ahi[mi].x),
                                   __float_as_uint(Alo[mi].y), __float_as_uint(Ahi[mi].y) };
                uint32_t a1[4] = { __float_as_uint(Alo[mi].z), __float_as_uint(Ahi[mi].z),
                                   __float_as_uint(Alo[mi].w), __float_as_uint(Ahi[mi].w) };
                #pragma unroll
                for (int nj = 0; nj < 4; nj++) {
                    mma_t(acc[mi][nj], a0, __float_as_uint(Bv[nj].x), __float_as_uint(Bv[nj].y));
                    mma_t(acc[mi][nj], a1, __float_as_uint(Bv[nj].z), __float_as_uint(Bv[nj].w));
                }
            }
        }
        __syncthreads();
        if (ch < 6) stage_cp(ch + 2, ch & 1);
    }

    #pragma unroll
    for (int nj = 0; nj < 4; nj++) {
        int c0 = wn*32 + nj*8 + lc*2;
        float bb0 = __ldg(&b1[c0]), bb1 = __ldg(&b1[c0+1]);
        float s0 = 0.f, s1 = 0.f, q0 = 0.f, q1 = 0.f;
        #pragma unroll
        for (int mi = 0; mi < 4; mi++) {
            int row = row0 + wm*64 + mi*16 + lr;
            float v0 = acc[mi][nj][0] + bb0;
            float v1 = acc[mi][nj][1] + bb1;
            float v2 = acc[mi][nj][2] + bb0;
            float v3 = acc[mi][nj][3] + bb1;
            *(float2*)&g_t[(size_t)row*64 + c0]     = make_float2(v0, v1);
            *(float2*)&g_t[(size_t)(row+8)*64 + c0] = make_float2(v2, v3);
            s0 += v0 + v2; s1 += v1 + v3;
            q0 += v0*v0 + v2*v2; q1 += v1*v1 + v3*v3;
        }
        atomicAdd(&scol[c0], s0);   atomicAdd(&scol[c0+1], s1);
        atomicAdd(&ssq[c0],  q0);   atomicAdd(&ssq[c0+1],  q1);
    }
    __syncthreads();
    if (tid < 64) {
        atomicAdd(&g_sum[tid],   scol[tid]);
        atomicAdd(&g_sumsq[tid], ssq[tid]);
    }
}

// ---------- kernel-gen (tf32 MMA, unchanged) ----------
__global__ __launch_bounds__(256) void k_mma_kg(const float* __restrict__ gamma,
                                                const float* __restrict__ beta,
                                                const float* __restrict__ w2,
                                                const float* __restrict__ b2) {
    __shared__ float As[128*SA];
    __shared__ float Bs[80*SA];
    __shared__ float sc[64], shf[64];
    int tid = threadIdx.x, wid = tid >> 5, lane = tid & 31;
    int lr = lane >> 2, lc = lane & 3;
    int wm = wid & 3, wn = wid >> 2;
    int row0 = blockIdx.x * 128;
    if (tid < 64) {
        const float invN = 1.0f / (float)Nn;
        float mu  = g_sum[tid] * invN;
        float var = g_sumsq[tid] * invN - mu * mu;
        float s = gamma[tid] * rsqrtf(var + EPSv);
        sc[tid]  = s;
        shf[tid] = beta[tid] - mu * s;
    }
    __syncthreads();

    float acc[2][5][4] = {};
    for (int ch = 0; ch < 2; ch++) {
        if (ch) __syncthreads();
        #pragma unroll
        for (int t = 0; t < 4; t++) {
            int idx = tid + t*256, r = idx >> 3, j = idx & 7;
            int c = ch*32 + j*4;
            float4 v = *(const float4*)&g_t[(size_t)(row0 + r)*64 + c];
            v.x = fmaxf(fmaf(v.x, sc[c+0], shf[c+0]), 0.f);
            v.y = fmaxf(fmaf(v.y, sc[c+1], shf[c+1]), 0.f);
            v.z = fmaxf(fmaf(v.z, sc[c+2], shf[c+2]), 0.f);
            v.w = fmaxf(fmaf(v.w, sc[c+3], shf[c+3]), 0.f);
            *(float4*)&As[r*SA + j*4] = tf4(v);
        }
        for (int idx = tid; idx < 80*8; idx += 256) {
            int r = idx >> 3, j = idx & 7;
            float4 v = make_float4(0.f, 0.f, 0.f, 0.f);
            if (r < 72) v = *(const float4*)&w2[(size_t)r*64 + ch*32 + j*4];
            *(float4*)&Bs[r*SA + j*4] = tf4(v);
        }
        __syncthreads();
        #pragma unroll
        for (int s = 0; s < 4; s++) {
            uint32_t a[2][4];
            #pragma unroll
            for (int mi = 0; mi < 2; mi++) {
                const float* Ap = &As[(wm*32 + mi*16 + lr)*SA + s*8 + lc];
                a[mi][0] = __float_as_uint(Ap[0]);
                a[mi][1] = __float_as_uint(Ap[8*SA]);
                a[mi][2] = __float_as_uint(Ap[4]);
                a[mi][3] = __float_as_uint(Ap[8*SA + 4]);
            }
            #pragma unroll
            for (int nj = 0; nj < 5; nj++) {
                const float* Bp = &Bs[(wn*40 + nj*8 + lr)*SA + s*8 + lc];
                uint32_t b0 = __float_as_uint(Bp[0]);
                uint32_t b1 = __float_as_uint(Bp[4]);
                mma_t(acc[0][nj], a[0], b0, b1);
                mma_t(acc[1][nj], a[1], b0, b1);
            }
        }
    }

    #pragma unroll
    for (int mi = 0; mi < 2; mi++) {
        int row = row0 + wm*32 + mi*16 + lr;
        #pragma unroll
        for (int nj = 0; nj < 5; nj++) {
            int col = wn*40 + nj*8 + lc*2;
            if (col < 72) {
                float bb0 = __ldg(&b2[col]), bb1 = __ldg(&b2[col+1]);
                *(float2*)&g_wk[(size_t)row*72 + col] =
                    make_float2(acc[mi][nj][0] + bb0, acc[mi][nj][1] + bb1);
                *(float2*)&g_wk[(size_t)(row+8)*72 + col] =
                    make_float2(acc[mi][nj][2] + bb0, acc[mi][nj][3] + bb1);
            }
        }
    }
}

// ---------- involution: 2 output rows per block ----------
__global__ __launch_bounds__(256) void k_invo3(const float* __restrict__ x) {
    __shared__ float xs[4][58][32];
    __shared__ float ws[2][56][9];
    int bi = blockIdx.x;               // b*28 + hp/2
    int g  = blockIdx.y;
    int b = bi / 28, hp = (bi % 28) * 2;
    int tid = threadIdx.x;

    {   // zero padding columns: 4 rows x 2 edges x 32 ch = 256
        int dy = tid >> 6, e = (tid >> 5) & 1, c = tid & 31;
        xs[dy][e ? 57 : 0][c] = 0.f;
    }
    for (int i = tid; i < 4*56*8; i += 256) {
        int c4 = i & 7, w = (i >> 3) % 56, dy = i / 448;
        int hh = hp + dy - 1;
        float4 v = make_float4(0.f, 0.f, 0.f, 0.f);
        if (hh >= 0 && hh < Hh)
            v = *(const float4*)&x[(((size_t)(b*Hh + hh))*Wd + w)*256 + g*32 + c4*4];
        *(float4*)&xs[dy][1 + w][c4*4] = v;
    }
    for (int i = tid; i < 2*56*9; i += 256) {
        int rr = i / (56*9), rem = i % (56*9), w = rem / 9, k = rem % 9;
        ws[rr][w][k] = g_wk[(((size_t)(b*Hh + hp + rr))*Wd + w)*72 + g*9 + k];
    }
    __syncthreads();

    int c = tid & 31, wq = tid >> 5;
    #pragma unroll
    for (int i = 0; i < 7; i++) {
        int w = wq + i*8;
        #pragma unroll
        for (int rr = 0; rr < 2; rr++) {
            float acc = 0.f;
            #pragma unroll
            for (int dy = 0; dy < 3; dy++)
                #pragma unroll
                for (int dx = 0; dx < 3; dx++)
                    acc += ws[rr][w][dy*3 + dx] * xs[rr + dy][w + dx][c];
            g_hw[(((size_t)(b*Hh + hp + rr))*Wd + w)*256 + g*32 + c] = acc;
        }
    }
}

// ================= cp.async 64x64-warp-tile GEMM core =================
__device__ __forceinline__ void gemm_core(const float* __restrict__ Ag,
                                          const float* __restrict__ Bg,
                                          int row0, int col0,
                                          float acc[4][8][4],
                                          float* dsm, uint32_t sbase,
                                          int tid, int wm, int wn, int lr, int lc) {
    auto stage_cp = [&](int ch, int s) {
        uint32_t sb0 = sbase + (uint32_t)(s * STGF * 4);
        int k0 = ch * 32;
        #pragma unroll
        for (int i = 0; i < 8; i++) {
            int idx = tid + i*128, r = idx >> 3, q = idx & 7;
            cp16(sb0 + (uint32_t)((r*ST + q*4)*4),
                 &Ag[(size_t)(row0 + r)*256 + k0 + q*4]);
        }
        #pragma unroll
        for (int i = 0; i < 8; i++) {
            int idx = tid + i*128, r = idx >> 3, q = idx & 7;
            cp16(sb0 + (uint32_t)((128*ST + r*ST + q*4)*4),
                 &Bg[(size_t)(col0 + r)*256 + k0 + q*4]);
        }
        CP_COMMIT();
    };
    stage_cp(0, 0);
    stage_cp(1, 1);

    for (int ch = 0; ch < 8; ch++) {
        if (ch < 7) CP_WAIT1(); else CP_WAIT0();
        __syncthreads();
        const float* Ab = dsm + (ch & 1) * STGF;
        const float* Bb = Ab + 128*ST;
        #pragma unroll
        for (int g = 0; g < 2; g++) {
            float4 Alo[4], Ahi[4], Bv[8];
            #pragma unroll
            for (int mi = 0; mi < 4; mi++) {
                Alo[mi] = *(const float4*)&Ab[(wm*64 + mi*16 + lr)*ST + g*16 + lc*4];
                Ahi[mi] = *(const float4*)&Ab[(wm*64 + mi*16 + 8 + lr)*ST + g*16 + lc*4];
            }
            #pragma unroll
            for (int nj = 0; nj < 8; nj++)
                Bv[nj] = *(const float4*)&Bb[(wn*64 + nj*8 + lr)*ST + g*16 + lc*4];
            #pragma unroll
            for (int mi = 0; mi < 4; mi++) {
                uint32_t a0[4] = { __float_as_uint(Alo[mi].x), __float_as_uint(Ahi[mi].x),
                                   __float_as_uint(Alo[mi].y), __float_as_uint(Ahi[mi].y) };
                uint32_t a1[4] = { __float_as_uint(Alo[mi].z), __float_as_uint(Ahi[mi].z),
                                   __float_as_uint(Alo[mi].w), __float_as_uint(Ahi[mi].w) };
                #pragma unroll
                for (int nj = 0; nj < 8; nj++) {
                    mma_t(acc[mi][nj], a0, __float_as_uint(Bv[nj].x), __float_as_uint(Bv[nj].y));
                    mma_t(acc[mi][nj], a1, __float_as_uint(Bv[nj].z), __float_as_uint(Bv[nj].w));
                }
            }
        }
        __syncthreads();
        if (ch < 6) stage_cp(ch + 2, ch & 1);
    }
}

// ---------- GEMM c = xr @ wmr^T  + fused (hw+c) spatial-mean ----------
__global__ __launch_bounds__(128) void k_mma_c2() {
    extern __shared__ float dsm[];
    __shared__ float scol[2][128];
    int tid = threadIdx.x, wid = tid >> 5, lane = tid & 31;
    int lr = lane >> 2, lc = lane & 3;
    int wm = wid >> 1, wn = wid & 1;
    int row0 = blockIdx.x * 128, col0 = blockIdx.y * 128;
    scol[0][tid] = 0.f; scol[1][tid] = 0.f;
    uint32_t sbase = smem_u32(dsm);

    float acc[4][8][4] = {};
    gemm_core(g_xr, g_wmr, row0, col0, acc, dsm, sbase, tid, wm, wn, lr, lc);

    int bimg = row0 / HWp;
    int bsplit = (bimg + 1) * HWp;
    #pragma unroll
    for (int nj = 0; nj < 8; nj++) {
        int colr = wn*64 + nj*8 + lc*2;
        int col = col0 + colr;
        float s0[2] = {0.f, 0.f}, s1[2] = {0.f, 0.f};
        #pragma unroll
        for (int mi = 0; mi < 4; mi++) {
            int row = row0 + wm*64 + mi*16 + lr;
            float2 c0 = make_float2(acc[mi][nj][0], acc[mi][nj][1]);
            float2 c1 = make_float2(acc[mi][nj][2], acc[mi][nj][3]);
            *(float2*)&g_cc[(size_t)row*256 + col]     = c0;
            *(float2*)&g_cc[(size_t)(row+8)*256 + col] = c1;
            float2 h0 = *(const float2*)&g_hw[(size_t)row*256 + col];
            float2 h1 = *(const float2*)&g_hw[(size_t)(row+8)*256 + col];
            int r0 = (row >= bsplit) ? 1 : 0;
            int r1 = (row + 8 >= bsplit) ? 1 : 0;
            s0[r0] += c0.x + h0.x;  s1[r0] += c0.y + h0.y;
            s0[r1] += c1.x + h1.x;  s1[r1] += c1.y + h1.y;
        }
        atomicAdd(&scol[0][colr],   s0[0]);
        atomicAdd(&scol[0][colr+1], s1[0]);
        if (s0[1] != 0.f || s1[1] != 0.f) {
            atomicAdd(&scol[1][colr],   s0[1]);
            atomicAdd(&scol[1][colr+1], s1[1]);
        }
    }
    __syncthreads();
    atomicAdd(&g_asum[bimg*256 + col0 + tid], scol[0][tid]);
    float v1 = scol[1][tid];
    if (v1 != 0.f && bimg + 1 < Bc)
        atomicAdd(&g_asum[(bimg+1)*256 + col0 + tid], v1);
}

// ---------- reweight MLP + pairwise softmax: one block per image ----------
__global__ __launch_bounds__(256) void k_small2(const float* __restrict__ fc1w,
                                                const float* __restrict__ fc1b,
                                                const float* __restrict__ fc2w,
                                                const float* __restrict__ fc2b) {
    __shared__ float sm[256];
    __shared__ float h1[64];
    int b = blockIdx.x, tid = threadIdx.x;
    sm[tid] = g_asum[b*256 + tid] * (1.0f / (float)HWp);
    __syncthreads();
    int o = tid >> 2, qtr = tid & 3;
    {
        const float* w = &fc1w[(size_t)o*256 + qtr*64];
        const float* s = &sm[qtr*64];
        float p = 0.f;
        #pragma unroll 8
        for (int c = 0; c < 64; c++) p += s[c] * w[c];
        p += __shfl_xor_sync(0xffffffffu, p, 1);
        p += __shfl_xor_sync(0xffffffffu, p, 2);
        if (qtr == 0) {
            float a = p + fc1b[o];
            h1[o] = 0.5f * a * (1.0f + erff(a * 0.70710678118654752f));
        }
    }
    __syncthreads();
    int c = tid;
    float l0 = fc2b[2*c], l1 = fc2b[2*c+1];
    #pragma unroll 8
    for (int k = 0; k < 64; k++) {
        float hv = h1[k];
        l0 += hv * fc2w[(size_t)(2*c)*64 + k];
        l1 += hv * fc2w[(size_t)(2*c+1)*64 + k];
    }
    float m = fmaxf(l0, l1);
    float e0 = expf(l0 - m), e1 = expf(l1 - m);
    float s = 1.f / (e0 + e1);
    g_a0[b*256 + c] = e0 * s;
    g_a1[b*256 + c] = e1 * s;
}

// ---------- y = rna(hw*a0 + cc*a1), permuted ----------
__global__ __launch_bounds__(256) void k_prey() {
    size_t idx = (size_t)blockIdx.x * 256 + threadIdx.x;
    int row = (int)(idx >> 4), g = (int)(idx & 15);
    size_t base = (size_t)row * 256 + g * 16;
    int bimg = row / HWp;
    const float* pa0 = &g_a0[bimg*256 + g*16];
    const float* pa1 = &g_a1[bimg*256 + g*16];
    float v[16];
    #pragma unroll
    for (int j = 0; j < 4; j++) {
        float4 hv = *(const float4*)&g_hw[base + j*4];
        float4 cv = *(const float4*)&g_cc[base + j*4];
        float4 a0 = *(const float4*)&pa0[j*4];
        float4 a1 = *(const float4*)&pa1[j*4];
        v[j*4+0] = hv.x*a0.x + cv.x*a1.x;
        v[j*4+1] = hv.y*a0.y + cv.y*a1.y;
        v[j*4+2] = hv.z*a0.z + cv.z*a1.z;
        v[j*4+3] = hv.w*a0.w + cv.w*a1.w;
    }
    #pragma unroll
    for (int j = 0; j < 4; j++)
        *(float4*)&g_y[base + j*4] = tf4(make_float4(v[j], v[4+j], v[8+j], v[12+j]));
}

// ---------- final GEMM: out = y @ wpr^T + bias ----------
__global__ __launch_bounds__(128) void k_mma_out2(const float* __restrict__ bp,
                                                  float* __restrict__ out) {
    extern __shared__ float dsm[];
    int tid = threadIdx.x, wid = tid >> 5, lane = tid & 31;
    int lr = lane >> 2, lc = lane & 3;
    int wm = wid >> 1, wn = wid & 1;
    int row0 = blockIdx.x * 128, col0 = blockIdx.y * 128;
    uint32_t sbase = smem_u32(dsm);

    float acc[4][8][4] = {};
    gemm_core(g_y, g_wpr, row0, col0, acc, dsm, sbase, tid, wm, wn, lr, lc);

    #pragma unroll
    for (int nj = 0; nj < 8; nj++) {
        int col = col0 + wn*64 + nj*8 + lc*2;
        float bb0 = __ldg(&bp[col]), bb1 = __ldg(&bp[col+1]);
        #pragma unroll
        for (int mi = 0; mi < 4; mi++) {
            int row = row0 + wm*64 + mi*16 + lr;
            *(float2*)&out[(size_t)row*256 + col] =
                make_float2(acc[mi][nj][0] + bb0, acc[mi][nj][1] + bb1);
            *(float2*)&out[(size_t)(row+8)*256 + col] =
                make_float2(acc[mi][nj][2] + bb0, acc[mi][nj][3] + bb1);
        }
    }
}

extern "C" void kernel_launch(void* const* d_in, const int* in_sizes, int n_in,
                              void* d_out, int out_size) {
    const float* x        = (const float*)d_in[0];
    const float* conv1_w  = (const float*)d_in[1];
    const float* conv1_b  = (const float*)d_in[2];
    const float* bn_gamma = (const float*)d_in[3];
    const float* bn_beta  = (const float*)d_in[4];
    const float* conv2_w  = (const float*)d_in[5];
    const float* conv2_b  = (const float*)d_in[6];
    const float* mlp_c_w  = (const float*)d_in[7];
    const float* fc1_w    = (const float*)d_in[8];
    const float* fc1_b    = (const float*)d_in[9];
    const float* fc2_w    = (const float*)d_in[10];
    const float* fc2_b    = (const float*)d_in[11];
    const float* projcnn_w= (const float*)d_in[12];
    const float* projcnn_b= (const float*)d_in[13];
    float* out = (float*)d_out;

    cudaFuncSetAttribute(k_mma_c2,   cudaFuncAttributeMaxDynamicSharedMemorySize, DSMC);
    cudaFuncSetAttribute(k_mma_out2, cudaFuncAttributeMaxDynamicSharedMemorySize, DSMC);
    cudaFuncSetAttribute(k_mma_g1b,  cudaFuncAttributeMaxDynamicSharedMemorySize, DSG1);

    k_zero   <<<1, 256>>>();
    k_round_x<<<Nn*16/256, 256>>>(x);
    k_round_w<<<36, 256>>>(mlp_c_w, projcnn_w, conv1_w);
    k_mma_g1b<<<Nn/128, 128, DSG1>>>(conv1_b);
    k_mma_kg <<<Nn/128, 256>>>(bn_gamma, bn_beta, conv2_w, conv2_b);
    k_invo3  <<<dim3(Bc*28, 8), 256>>>(x);
    k_mma_c2 <<<dim3(Nn/128, 2), 128, DSMC>>>();
    k_small2 <<<Bc, 256>>>(fc1_w, fc1_b, fc2_w, fc2_b);
    k_prey   <<<Nn*16/256, 256>>>();
    k_mma_out2<<<dim3(Nn/128, 2), 128, DSMC>>>(projcnn_b, out);
}